// round 2
// baseline (speedup 1.0000x reference)
#include <cuda_runtime.h>
#include <cstddef>

// ---------------------------------------------------------------------------
// GATLayer: out = relu( MHA_masked(x; Wq,Wk,Wv, adj) ) @ Wo
// B=8, N=1024, D=512, NH=8, DK=64
// Inputs (metadata order): x[f32 B,N,D], adj[i32 B,N,N], Wq,Wk,Wv,Wo [f32 D,D]
// Output: f32 [B,N,D]
// ---------------------------------------------------------------------------

#define Bb   8
#define Nn   1024
#define Dd   512
#define NH   8
#define DK   64
#define MROWS (Bb * Nn)          // 8192

// Scratch: head-major Q/K/V [ (b*NH+h) ][ n ][ dk ], and attention output in
// [b][n][h*DK+dk] (row-major 8192x512) for the final GEMM.
__device__ float g_Q[Bb * NH * Nn * DK];
__device__ float g_K[Bb * NH * Nn * DK];
__device__ float g_V[Bb * NH * Nn * DK];
__device__ float g_att[MROWS * Dd];

// ---------------------------------------------------------------------------
// GEMM: C[M,512] = op(A[M,512]) @ W[512,512]
// TILE 128x64, BK=16, 256 threads, 8x4 micro-tile.
// MODE 0: scatter output to head-major Q/K/V layout.
// MODE 1: relu on A load, plain row-major output.
// ---------------------------------------------------------------------------
#define TM 128
#define TN 64
#define TK 16

template <int MODE>
__global__ __launch_bounds__(256, 2)
void gemm_kernel(const float* __restrict__ A, const float* __restrict__ W,
                 float* __restrict__ C) {
    __shared__ float AsT[TK][TM + 4];   // transposed A tile, 16 x 132
    __shared__ float Bs[TK][TN + 4];    // 16 x 68

    const int t  = threadIdx.x;
    const int ty = t >> 4;              // 0..15 (row group of 8)
    const int tx = t & 15;              // 0..15 (col group of 4)
    const int m0 = blockIdx.x * TM;
    const int n0 = blockIdx.y * TN;

    float acc[8][4];
#pragma unroll
    for (int i = 0; i < 8; i++)
#pragma unroll
        for (int j = 0; j < 4; j++) acc[i][j] = 0.f;

    const int arow = t >> 2;            // 0..63
    const int ac4  = t & 3;             // float4 slot in 16-col chunk
    const int brow = t >> 4;            // 0..15
    const int bc4  = t & 15;            // 0..15

    for (int k0 = 0; k0 < Dd; k0 += TK) {
        // A tile: rows m0..+127, cols k0..+15 (transposed into smem)
#pragma unroll
        for (int r = 0; r < 2; r++) {
            int row = arow + 64 * r;
            float4 a = *(const float4*)(A + (size_t)(m0 + row) * Dd + k0 + ac4 * 4);
            if (MODE == 1) {
                a.x = fmaxf(a.x, 0.f); a.y = fmaxf(a.y, 0.f);
                a.z = fmaxf(a.z, 0.f); a.w = fmaxf(a.w, 0.f);
            }
            AsT[ac4 * 4 + 0][row] = a.x;
            AsT[ac4 * 4 + 1][row] = a.y;
            AsT[ac4 * 4 + 2][row] = a.z;
            AsT[ac4 * 4 + 3][row] = a.w;
        }
        // B tile: rows k0..+15, cols n0..+63
        {
            float4 bvec = *(const float4*)(W + (size_t)(k0 + brow) * Dd + n0 + bc4 * 4);
            *(float4*)&Bs[brow][bc4 * 4] = bvec;
        }
        __syncthreads();

#pragma unroll
        for (int k = 0; k < TK; k++) {
            float4 a0 = *(float4*)&AsT[k][ty * 8];
            float4 a1 = *(float4*)&AsT[k][ty * 8 + 4];
            float4 bb = *(float4*)&Bs[k][tx * 4];
            float av[8] = {a0.x, a0.y, a0.z, a0.w, a1.x, a1.y, a1.z, a1.w};
            float bv[4] = {bb.x, bb.y, bb.z, bb.w};
#pragma unroll
            for (int i = 0; i < 8; i++)
#pragma unroll
                for (int j = 0; j < 4; j++) acc[i][j] += av[i] * bv[j];
        }
        __syncthreads();
    }

    // Epilogue
    if (MODE == 0) {
        // col block n0..n0+63 lies entirely within one head
        const int h  = n0 >> 6;
        const int dk = tx * 4;
#pragma unroll
        for (int i = 0; i < 8; i++) {
            int m = m0 + ty * 8 + i;
            int bI = m >> 10;
            int n  = m & 1023;
            float4 v = make_float4(acc[i][0], acc[i][1], acc[i][2], acc[i][3]);
            *(float4*)(C + ((size_t)((bI * NH + h) * Nn + n)) * DK + dk) = v;
        }
    } else {
#pragma unroll
        for (int i = 0; i < 8; i++) {
            int m = m0 + ty * 8 + i;
            float4 v = make_float4(acc[i][0], acc[i][1], acc[i][2], acc[i][3]);
            *(float4*)(C + (size_t)m * Dd + n0 + tx * 4) = v;
        }
    }
}

// ---------------------------------------------------------------------------
// Flash-attention style masked attention.
// Grid: (N/64, B*NH). Block: 256 threads. Q tile 64, key tile 32.
// Online softmax with adjacency mask (masked score = -1e30, NaN-safe).
// ---------------------------------------------------------------------------
__global__ __launch_bounds__(256, 2)
void attn_kernel(const float* __restrict__ Q, const float* __restrict__ K,
                 const float* __restrict__ V, const int* __restrict__ adj,
                 float* __restrict__ Oatt) {
    __shared__ float QsT[64][68];       // [d][q]
    __shared__ float KsT[64][36];       // [d][k]
    __shared__ float Vs[32][68];        // [k][d]
    __shared__ float Ss[32][68];        // [k][q]  scores then probabilities
    __shared__ float m_s[64], l_s[64], alpha_s[64];

    const int t  = threadIdx.x;
    const int ty = t >> 4;              // 0..15
    const int tx = t & 15;              // 0..15
    const int bh = blockIdx.y;          // b*NH + h
    const int bI = bh >> 3;
    const int h  = bh & 7;
    const int q0 = blockIdx.x * 64;

    const float* Qb = Q + (size_t)bh * Nn * DK;
    const float* Kb = K + (size_t)bh * Nn * DK;
    const float* Vb = V + (size_t)bh * Nn * DK;
    const int* adjb = adj + (size_t)bI * Nn * Nn;

    // Load Q tile [64 x 64] transposed
#pragma unroll
    for (int r = 0; r < 4; r++) {
        int idx = t + 256 * r;          // 0..1023
        int row = idx >> 4;             // 0..63
        int c4  = idx & 15;
        float4 v = *(const float4*)(Qb + (size_t)(q0 + row) * DK + c4 * 4);
        QsT[c4 * 4 + 0][row] = v.x;
        QsT[c4 * 4 + 1][row] = v.y;
        QsT[c4 * 4 + 2][row] = v.z;
        QsT[c4 * 4 + 3][row] = v.w;
    }
    if (t < 64) { m_s[t] = -1e30f; l_s[t] = 0.f; }

    float acc[4][4];
#pragma unroll
    for (int i = 0; i < 4; i++)
#pragma unroll
        for (int j = 0; j < 4; j++) acc[i][j] = 0.f;

    for (int k0 = 0; k0 < Nn; k0 += 32) {
        __syncthreads();   // prev iter's reads of Ss/Vs/KsT done; Q ready (1st)
        // Load K tile transposed + V tile: 32 rows x 64 cols each
#pragma unroll
        for (int r = 0; r < 2; r++) {
            int idx = t + 256 * r;      // 0..511
            int row = idx >> 4;         // 0..31
            int c4  = idx & 15;
            float4 kv = *(const float4*)(Kb + (size_t)(k0 + row) * DK + c4 * 4);
            KsT[c4 * 4 + 0][row] = kv.x;
            KsT[c4 * 4 + 1][row] = kv.y;
            KsT[c4 * 4 + 2][row] = kv.z;
            KsT[c4 * 4 + 3][row] = kv.w;
            float4 vv = *(const float4*)(Vb + (size_t)(k0 + row) * DK + c4 * 4);
            *(float4*)&Vs[row][c4 * 4] = vv;
        }
        __syncthreads();

        // S = Q @ K^T : each thread 4q x 2k
        float s[4][2] = {{0.f, 0.f}, {0.f, 0.f}, {0.f, 0.f}, {0.f, 0.f}};
#pragma unroll
        for (int d = 0; d < 64; d++) {
            float4 a = *(float4*)&QsT[d][ty * 4];
            float b0 = KsT[d][tx * 2];
            float b1 = KsT[d][tx * 2 + 1];
            s[0][0] += a.x * b0; s[0][1] += a.x * b1;
            s[1][0] += a.y * b0; s[1][1] += a.y * b1;
            s[2][0] += a.z * b0; s[2][1] += a.z * b1;
            s[3][0] += a.w * b0; s[3][1] += a.w * b1;
        }
        // scale + mask + store transposed into Ss[k][q]
#pragma unroll
        for (int i = 0; i < 4; i++) {
            const int* arow = adjb + (size_t)(q0 + ty * 4 + i) * Nn + k0;
#pragma unroll
            for (int j = 0; j < 2; j++) {
                int kk = tx * 2 + j;
                float val = arow[kk] ? s[i][j] * 0.125f : -1e30f;
                Ss[kk][ty * 4 + i] = val;
            }
        }
        __syncthreads();

        // Online softmax (one thread per query row)
        if (t < 64) {
            const int q = t;
            float mb = -1e30f;
#pragma unroll
            for (int k = 0; k < 32; k++) mb = fmaxf(mb, Ss[k][q]);
            float mo = m_s[q];
            float mn = fmaxf(mo, mb);
            float sum = 0.f;
#pragma unroll
            for (int k = 0; k < 32; k++) {
                float p = __expf(Ss[k][q] - mn);
                Ss[k][q] = p;
                sum += p;
            }
            float al = __expf(mo - mn);
            l_s[q] = l_s[q] * al + sum;
            m_s[q] = mn;
            alpha_s[q] = al;
        }
        __syncthreads();

        // acc = acc*alpha + P @ V
        float al[4];
#pragma unroll
        for (int i = 0; i < 4; i++) al[i] = alpha_s[ty * 4 + i];
#pragma unroll
        for (int i = 0; i < 4; i++)
#pragma unroll
            for (int j = 0; j < 4; j++) acc[i][j] *= al[i];
#pragma unroll
        for (int k = 0; k < 32; k++) {
            float4 p = *(float4*)&Ss[k][ty * 4];
            float4 v = *(float4*)&Vs[k][tx * 4];
            float pv[4] = {p.x, p.y, p.z, p.w};
            float vv[4] = {v.x, v.y, v.z, v.w};
#pragma unroll
            for (int i = 0; i < 4; i++)
#pragma unroll
                for (int j = 0; j < 4; j++) acc[i][j] += pv[i] * vv[j];
        }
    }

    // Epilogue: normalize and write [b][n][h*DK + dk]
#pragma unroll
    for (int i = 0; i < 4; i++) {
        int q = ty * 4 + i;
        float inv = 1.f / l_s[q];
        int n = q0 + q;
        float4 o = make_float4(acc[i][0] * inv, acc[i][1] * inv,
                               acc[i][2] * inv, acc[i][3] * inv);
        *(float4*)(Oatt + ((size_t)(bI * Nn + n)) * Dd + h * DK + tx * 4) = o;
    }
}

// ---------------------------------------------------------------------------
extern "C" void kernel_launch(void* const* d_in, const int* in_sizes, int n_in,
                              void* d_out, int out_size) {
    const float* x   = (const float*)d_in[0];
    const int*   adj = (const int*)d_in[1];
    const float* Wq  = (const float*)d_in[2];
    const float* Wk  = (const float*)d_in[3];
    const float* Wv  = (const float*)d_in[4];
    const float* Wo  = (const float*)d_in[5];
    float* out = (float*)d_out;

    float *pQ, *pK, *pV, *pAtt;
    cudaGetSymbolAddress((void**)&pQ, g_Q);
    cudaGetSymbolAddress((void**)&pK, g_K);
    cudaGetSymbolAddress((void**)&pV, g_V);
    cudaGetSymbolAddress((void**)&pAtt, g_att);

    dim3 gg(MROWS / TM, Dd / TN);   // 64 x 8
    gemm_kernel<0><<<gg, 256>>>(x, Wq, pQ);
    gemm_kernel<0><<<gg, 256>>>(x, Wk, pK);
    gemm_kernel<0><<<gg, 256>>>(x, Wv, pV);

    attn_kernel<<<dim3(Nn / 64, Bb * NH), 256>>>(pQ, pK, pV, adj, pAtt);

    gemm_kernel<1><<<gg, 256>>>(pAtt, Wo, out);
}

// round 4
// speedup vs baseline: 1.2886x; 1.2886x over previous
#include <cuda_runtime.h>
#include <cuda_bf16.h>
#include <cstdint>
#include <cstddef>

// ---------------------------------------------------------------------------
// GATLayer: out = relu( MHA_masked(x; Wq,Wk,Wv, adj) ) @ Wo
// B=8, N=1024, D=512, NH=8, DK=64
// Round 3: dense GEMMs via mma.sync bf16 (hi/lo x3 split, fp32-grade accuracy).
// (tcgen05 unavailable: harness compiles PTX for sm_100 baseline, not 100a.)
// Attention unchanged (SIMT fp32) - tensorized next round.
// ---------------------------------------------------------------------------

#define Bb   8
#define Nn   1024
#define Dd   512
#define NH   8
#define DK   64
#define MROWS (Bb * Nn)          // 8192

// ---------------- scratch ----------------
__device__ __nv_bfloat16 g_xh[MROWS * Dd];
__device__ __nv_bfloat16 g_xl[MROWS * Dd];
__device__ __nv_bfloat16 g_Wth[3 * Dd * Dd];   // packed [Wq^T;Wk^T;Wv^T] rows=1536
__device__ __nv_bfloat16 g_Wtl[3 * Dd * Dd];
__device__ __nv_bfloat16 g_Woth[Dd * Dd];      // Wo^T
__device__ __nv_bfloat16 g_Wotl[Dd * Dd];
__device__ float g_Q[Bb * NH * Nn * DK];
__device__ float g_K[Bb * NH * Nn * DK];
__device__ float g_V[Bb * NH * Nn * DK];
__device__ float g_att[MROWS * Dd];
__device__ __nv_bfloat16 g_atth[MROWS * Dd];
__device__ __nv_bfloat16 g_attl[MROWS * Dd];

// ---------------------------------------------------------------------------
// mma.sync m16n8k16 bf16 (fp32 accum) - baseline PTX, works on sm_100 target.
// ---------------------------------------------------------------------------
__device__ __forceinline__ void mma_bf16(float* c, const uint32_t* a, const uint32_t* b) {
    asm volatile(
        "mma.sync.aligned.m16n8k16.row.col.f32.bf16.bf16.f32 "
        "{%0,%1,%2,%3}, {%4,%5,%6,%7}, {%8,%9}, {%0,%1,%2,%3};"
        : "+f"(c[0]), "+f"(c[1]), "+f"(c[2]), "+f"(c[3])
        : "r"(a[0]), "r"(a[1]), "r"(a[2]), "r"(a[3]), "r"(b[0]), "r"(b[1]));
}

// ---------------------------------------------------------------------------
// split: f32 -> bf16 hi + bf16 lo (optionally relu first). float4-vectorized.
// ---------------------------------------------------------------------------
__global__ void split_kernel(const float* __restrict__ in,
                             __nv_bfloat16* __restrict__ hi,
                             __nv_bfloat16* __restrict__ lo,
                             int n4, int relu) {
    int i = blockIdx.x * blockDim.x + threadIdx.x;
    if (i >= n4) return;
    float4 v = ((const float4*)in)[i];
    if (relu) {
        v.x = fmaxf(v.x, 0.f); v.y = fmaxf(v.y, 0.f);
        v.z = fmaxf(v.z, 0.f); v.w = fmaxf(v.w, 0.f);
    }
    __nv_bfloat16 h0 = __float2bfloat16(v.x), h1 = __float2bfloat16(v.y);
    __nv_bfloat16 h2 = __float2bfloat16(v.z), h3 = __float2bfloat16(v.w);
    __nv_bfloat16 l0 = __float2bfloat16(v.x - __bfloat162float(h0));
    __nv_bfloat16 l1 = __float2bfloat16(v.y - __bfloat162float(h1));
    __nv_bfloat16 l2 = __float2bfloat16(v.z - __bfloat162float(h2));
    __nv_bfloat16 l3 = __float2bfloat16(v.w - __bfloat162float(h3));
    __nv_bfloat162* H = (__nv_bfloat162*)hi;
    __nv_bfloat162* L = (__nv_bfloat162*)lo;
    H[2 * i]     = __nv_bfloat162(h0, h1);
    H[2 * i + 1] = __nv_bfloat162(h2, h3);
    L[2 * i]     = __nv_bfloat162(l0, l1);
    L[2 * i + 1] = __nv_bfloat162(l2, l3);
}

// transpose + split weights: W[k][n] (f32, 512x512) -> T[rowoff+n][k] hi/lo
__global__ void wsplit_kernel(const float* __restrict__ W,
                              __nv_bfloat16* __restrict__ th,
                              __nv_bfloat16* __restrict__ tl, int rowoff) {
    int t = blockIdx.x * blockDim.x + threadIdx.x;   // 512*512 threads
    int k = t & 511, n = t >> 9;
    float v = W[(size_t)k * Dd + n];
    __nv_bfloat16 h = __float2bfloat16(v);
    __nv_bfloat16 l = __float2bfloat16(v - __bfloat162float(h));
    th[(size_t)(rowoff + n) * Dd + k] = h;
    tl[(size_t)(rowoff + n) * Dd + k] = l;
}

// ---------------------------------------------------------------------------
// HMMA GEMM: C[M=8192, Ntot] = A[8192,512] @ Bt[Ntot,512]^T
// A,Bt as bf16 hi/lo; C = Ah*Bh + Ah*Bl + Al*Bh (fp32 accum).
// CTA 128x64, BK=32, 256 thr = 8 warps (4m x 2n), warp tile 32x32.
// MODE 0: scatter to head-major Q/K/V (Ntot=1536). MODE 1: row-major (Ntot=512).
// ---------------------------------------------------------------------------
#define LDS_K 40                 // padded row length (elements); 80B stride

template <int MODE>
__global__ __launch_bounds__(256)
void gemm_hmma(const __nv_bfloat16* __restrict__ Ah, const __nv_bfloat16* __restrict__ Al,
               const __nv_bfloat16* __restrict__ Bh, const __nv_bfloat16* __restrict__ Bl,
               float* __restrict__ C0, float* __restrict__ C1, float* __restrict__ C2) {
    __shared__ __align__(16) __nv_bfloat16 sAh[128 * LDS_K];
    __shared__ __align__(16) __nv_bfloat16 sAl[128 * LDS_K];
    __shared__ __align__(16) __nv_bfloat16 sBh[64 * LDS_K];
    __shared__ __align__(16) __nv_bfloat16 sBl[64 * LDS_K];

    const int t    = threadIdx.x;
    const int wid  = t >> 5;
    const int lane = t & 31;
    const int g    = lane >> 2;      // fragment row group 0..7
    const int tig  = lane & 3;       // thread-in-group
    const int wm   = wid & 3;        // warp m index (0..3) -> rows wm*32
    const int wn   = wid >> 2;       // warp n index (0..1) -> cols wn*32
    const int m0   = blockIdx.x * 128;
    const int n0   = blockIdx.y * 64;

    const uint4* gAh = (const uint4*)Ah;   // 64 uint4 per 512-col row
    const uint4* gAl = (const uint4*)Al;
    const uint4* gBh = (const uint4*)Bh;
    const uint4* gBl = (const uint4*)Bl;

    float acc[2][4][4];
#pragma unroll
    for (int i = 0; i < 2; i++)
#pragma unroll
        for (int j = 0; j < 4; j++)
#pragma unroll
            for (int e = 0; e < 4; e++) acc[i][j][e] = 0.f;

    const uint32_t* sAh32 = (const uint32_t*)sAh;
    const uint32_t* sAl32 = (const uint32_t*)sAl;
    const uint32_t* sBh32 = (const uint32_t*)sBh;
    const uint32_t* sBl32 = (const uint32_t*)sBl;
    const int LW = LDS_K / 2;        // 20 words per row

    for (int c = 0; c < 16; c++) {   // K chunks of 32
        // ---- global -> smem (uint4 = 8 bf16) ----
#pragma unroll
        for (int i = 0; i < 2; i++) {
            int idx = t + 256 * i;          // 0..511
            int r = idx >> 2, j = idx & 3;  // 128 rows x 4 uint4
            size_t gofs = (size_t)(m0 + r) * 64 + c * 4 + j;
            *(uint4*)(sAh + r * LDS_K + j * 8) = gAh[gofs];
            *(uint4*)(sAl + r * LDS_K + j * 8) = gAl[gofs];
        }
        {
            int r = t >> 2, j = t & 3;      // 64 rows x 4 uint4
            size_t gofs = (size_t)(n0 + r) * 64 + c * 4 + j;
            *(uint4*)(sBh + r * LDS_K + j * 8) = gBh[gofs];
            *(uint4*)(sBl + r * LDS_K + j * 8) = gBl[gofs];
        }
        __syncthreads();

#pragma unroll
        for (int ks = 0; ks < 2; ks++) {     // two k16 steps, word offset kw
            const int kw = ks * 8;
            uint32_t ah[2][4], al[2][4], bh[4][2], bl[4][2];
#pragma unroll
            for (int i = 0; i < 2; i++) {
                int row = wm * 32 + i * 16 + g;
                ah[i][0] = sAh32[row * LW + kw + tig];
                ah[i][1] = sAh32[(row + 8) * LW + kw + tig];
                ah[i][2] = sAh32[row * LW + kw + 4 + tig];
                ah[i][3] = sAh32[(row + 8) * LW + kw + 4 + tig];
                al[i][0] = sAl32[row * LW + kw + tig];
                al[i][1] = sAl32[(row + 8) * LW + kw + tig];
                al[i][2] = sAl32[row * LW + kw + 4 + tig];
                al[i][3] = sAl32[(row + 8) * LW + kw + 4 + tig];
            }
#pragma unroll
            for (int j = 0; j < 4; j++) {
                int row = wn * 32 + j * 8 + g;
                bh[j][0] = sBh32[row * LW + kw + tig];
                bh[j][1] = sBh32[row * LW + kw + 4 + tig];
                bl[j][0] = sBl32[row * LW + kw + tig];
                bl[j][1] = sBl32[row * LW + kw + 4 + tig];
            }
#pragma unroll
            for (int i = 0; i < 2; i++)
#pragma unroll
                for (int j = 0; j < 4; j++) {
                    mma_bf16(acc[i][j], ah[i], bh[j]);
                    mma_bf16(acc[i][j], ah[i], bl[j]);
                    mma_bf16(acc[i][j], al[i], bh[j]);
                }
        }
        __syncthreads();
    }

    // ---- epilogue ----
#pragma unroll
    for (int i = 0; i < 2; i++) {
#pragma unroll
        for (int j = 0; j < 4; j++) {
            int row0 = m0 + wm * 32 + i * 16 + g;
            int col  = n0 + wn * 32 + j * 8 + tig * 2;
            float* dst0;
            float* dst1;
            if (MODE == 0) {
                const int mat = n0 >> 9;          // 0=Q,1=K,2=V
                const int cc  = col & 511;
                const int h   = cc >> 6;
                const int dk  = cc & 63;
                float* base = (mat == 0 ? C0 : (mat == 1 ? C1 : C2));
                int bI0 = row0 >> 10, nn0 = row0 & 1023;
                int r1 = row0 + 8;
                int bI1 = r1 >> 10, nn1 = r1 & 1023;
                dst0 = base + ((size_t)((bI0 * NH + h) * Nn + nn0)) * DK + dk;
                dst1 = base + ((size_t)((bI1 * NH + h) * Nn + nn1)) * DK + dk;
            } else {
                dst0 = C0 + (size_t)row0 * Dd + col;
                dst1 = C0 + (size_t)(row0 + 8) * Dd + col;
            }
            *(float2*)dst0 = make_float2(acc[i][j][0], acc[i][j][1]);
            *(float2*)dst1 = make_float2(acc[i][j][2], acc[i][j][3]);
        }
    }
}

// ---------------------------------------------------------------------------
// Flash-attention style masked attention (unchanged; passing baseline).
// ---------------------------------------------------------------------------
__global__ __launch_bounds__(256, 2)
void attn_kernel(const float* __restrict__ Q, const float* __restrict__ K,
                 const float* __restrict__ V, const int* __restrict__ adj,
                 float* __restrict__ Oatt) {
    __shared__ float QsT[64][68];
    __shared__ float KsT[64][36];
    __shared__ float Vs[32][68];
    __shared__ float Ss[32][68];
    __shared__ float m_s[64], l_s[64], alpha_s[64];

    const int t  = threadIdx.x;
    const int ty = t >> 4;
    const int tx = t & 15;
    const int bh = blockIdx.y;
    const int bI = bh >> 3;
    const int h  = bh & 7;
    const int q0 = blockIdx.x * 64;

    const float* Qb = Q + (size_t)bh * Nn * DK;
    const float* Kb = K + (size_t)bh * Nn * DK;
    const float* Vb = V + (size_t)bh * Nn * DK;
    const int* adjb = adj + (size_t)bI * Nn * Nn;

#pragma unroll
    for (int r = 0; r < 4; r++) {
        int idx = t + 256 * r;
        int row = idx >> 4;
        int c4  = idx & 15;
        float4 v = *(const float4*)(Qb + (size_t)(q0 + row) * DK + c4 * 4);
        QsT[c4 * 4 + 0][row] = v.x;
        QsT[c4 * 4 + 1][row] = v.y;
        QsT[c4 * 4 + 2][row] = v.z;
        QsT[c4 * 4 + 3][row] = v.w;
    }
    if (t < 64) { m_s[t] = -1e30f; l_s[t] = 0.f; }

    float acc[4][4];
#pragma unroll
    for (int i = 0; i < 4; i++)
#pragma unroll
        for (int j = 0; j < 4; j++) acc[i][j] = 0.f;

    for (int k0 = 0; k0 < Nn; k0 += 32) {
        __syncthreads();
#pragma unroll
        for (int r = 0; r < 2; r++) {
            int idx = t + 256 * r;
            int row = idx >> 4;
            int c4  = idx & 15;
            float4 kv = *(const float4*)(Kb + (size_t)(k0 + row) * DK + c4 * 4);
            KsT[c4 * 4 + 0][row] = kv.x;
            KsT[c4 * 4 + 1][row] = kv.y;
            KsT[c4 * 4 + 2][row] = kv.z;
            KsT[c4 * 4 + 3][row] = kv.w;
            float4 vv = *(const float4*)(Vb + (size_t)(k0 + row) * DK + c4 * 4);
            *(float4*)&Vs[row][c4 * 4] = vv;
        }
        __syncthreads();

        float s[4][2] = {{0.f, 0.f}, {0.f, 0.f}, {0.f, 0.f}, {0.f, 0.f}};
#pragma unroll
        for (int d = 0; d < 64; d++) {
            float4 a = *(float4*)&QsT[d][ty * 4];
            float b0 = KsT[d][tx * 2];
            float b1 = KsT[d][tx * 2 + 1];
            s[0][0] += a.x * b0; s[0][1] += a.x * b1;
            s[1][0] += a.y * b0; s[1][1] += a.y * b1;
            s[2][0] += a.z * b0; s[2][1] += a.z * b1;
            s[3][0] += a.w * b0; s[3][1] += a.w * b1;
        }
#pragma unroll
        for (int i = 0; i < 4; i++) {
            const int* arow = adjb + (size_t)(q0 + ty * 4 + i) * Nn + k0;
#pragma unroll
            for (int j = 0; j < 2; j++) {
                int kk = tx * 2 + j;
                float val = arow[kk] ? s[i][j] * 0.125f : -1e30f;
                Ss[kk][ty * 4 + i] = val;
            }
        }
        __syncthreads();

        if (t < 64) {
            const int q = t;
            float mb = -1e30f;
#pragma unroll
            for (int k = 0; k < 32; k++) mb = fmaxf(mb, Ss[k][q]);
            float mo = m_s[q];
            float mn = fmaxf(mo, mb);
            float sum = 0.f;
#pragma unroll
            for (int k = 0; k < 32; k++) {
                float p = __expf(Ss[k][q] - mn);
                Ss[k][q] = p;
                sum += p;
            }
            float al = __expf(mo - mn);
            l_s[q] = l_s[q] * al + sum;
            m_s[q] = mn;
            alpha_s[q] = al;
        }
        __syncthreads();

        float al[4];
#pragma unroll
        for (int i = 0; i < 4; i++) al[i] = alpha_s[ty * 4 + i];
#pragma unroll
        for (int i = 0; i < 4; i++)
#pragma unroll
            for (int j = 0; j < 4; j++) acc[i][j] *= al[i];
#pragma unroll
        for (int k = 0; k < 32; k++) {
            float4 p = *(float4*)&Ss[k][ty * 4];
            float4 v = *(float4*)&Vs[k][tx * 4];
            float pv[4] = {p.x, p.y, p.z, p.w};
            float vv[4] = {v.x, v.y, v.z, v.w};
#pragma unroll
            for (int i = 0; i < 4; i++)
#pragma unroll
                for (int j = 0; j < 4; j++) acc[i][j] += pv[i] * vv[j];
        }
    }

#pragma unroll
    for (int i = 0; i < 4; i++) {
        int q = ty * 4 + i;
        float inv = 1.f / l_s[q];
        int n = q0 + q;
        float4 o = make_float4(acc[i][0] * inv, acc[i][1] * inv,
                               acc[i][2] * inv, acc[i][3] * inv);
        *(float4*)(Oatt + ((size_t)(bI * Nn + n)) * Dd + h * DK + tx * 4) = o;
    }
}

// ---------------------------------------------------------------------------
extern "C" void kernel_launch(void* const* d_in, const int* in_sizes, int n_in,
                              void* d_out, int out_size) {
    const float* x   = (const float*)d_in[0];
    const int*   adj = (const int*)d_in[1];
    const float* Wq  = (const float*)d_in[2];
    const float* Wk  = (const float*)d_in[3];
    const float* Wv  = (const float*)d_in[4];
    const float* Wo  = (const float*)d_in[5];
    float* out = (float*)d_out;

    float *pQ, *pK, *pV, *pAtt;
    __nv_bfloat16 *pxh, *pxl, *pWth, *pWtl, *pWoth, *pWotl, *patth, *pattl;
    cudaGetSymbolAddress((void**)&pQ, g_Q);
    cudaGetSymbolAddress((void**)&pK, g_K);
    cudaGetSymbolAddress((void**)&pV, g_V);
    cudaGetSymbolAddress((void**)&pAtt, g_att);
    cudaGetSymbolAddress((void**)&pxh, g_xh);
    cudaGetSymbolAddress((void**)&pxl, g_xl);
    cudaGetSymbolAddress((void**)&pWth, g_Wth);
    cudaGetSymbolAddress((void**)&pWtl, g_Wtl);
    cudaGetSymbolAddress((void**)&pWoth, g_Woth);
    cudaGetSymbolAddress((void**)&pWotl, g_Wotl);
    cudaGetSymbolAddress((void**)&patth, g_atth);
    cudaGetSymbolAddress((void**)&pattl, g_attl);

    const int n4 = MROWS * Dd / 4;   // 1,048,576 float4 elements

    // operand prep
    split_kernel<<<n4 / 256, 256>>>(x, pxh, pxl, n4, 0);
    wsplit_kernel<<<1024, 256>>>(Wq, pWth, pWtl, 0);
    wsplit_kernel<<<1024, 256>>>(Wk, pWth, pWtl, 512);
    wsplit_kernel<<<1024, 256>>>(Wv, pWth, pWtl, 1024);
    wsplit_kernel<<<1024, 256>>>(Wo, pWoth, pWotl, 0);

    // fused QKV GEMM -> head-major Q/K/V (f32)
    gemm_hmma<0><<<dim3(MROWS / 128, 1536 / 64), 256>>>(
        pxh, pxl, pWth, pWtl, pQ, pK, pV);

    // masked attention (SIMT fp32, unchanged)
    attn_kernel<<<dim3(Nn / 64, Bb * NH), 256>>>(pQ, pK, pV, adj, pAtt);

    // relu + split, then output GEMM
    split_kernel<<<n4 / 256, 256>>>(pAtt, patth, pattl, n4, 1);
    gemm_hmma<1><<<dim3(MROWS / 128, Dd / 64), 256>>>(
        patth, pattl, pWoth, pWotl, out, nullptr, nullptr);
}

// round 5
// speedup vs baseline: 1.9933x; 1.5469x over previous
#include <cuda_runtime.h>
#include <cuda_bf16.h>
#include <cstdint>
#include <cstddef>

// ---------------------------------------------------------------------------
// GATLayer: out = relu( MHA_masked(x; Wq,Wk,Wv, adj) ) @ Wo
// B=8, N=1024, D=512, NH=8, DK=64
// Round 4: everything on HMMA (mma.sync bf16 hi/lo x3). Attention tensorized:
//   S=QK^T (3-term), register online softmax (quad shfl), thread-local P
//   repack, PV (3-term). Ballot-packed adjacency masks. relu+split fused
//   into attention epilogue; QKV GEMM writes bf16 hi/lo directly.
// ---------------------------------------------------------------------------

#define Bb   8
#define Nn   1024
#define Dd   512
#define NH   8
#define DK   64
#define MROWS (Bb * Nn)          // 8192

// ---------------- scratch ----------------
__device__ __nv_bfloat16 g_xh[MROWS * Dd];
__device__ __nv_bfloat16 g_xl[MROWS * Dd];
__device__ __nv_bfloat16 g_Wth[3 * Dd * Dd];   // packed [Wq^T;Wk^T;Wv^T]
__device__ __nv_bfloat16 g_Wtl[3 * Dd * Dd];
__device__ __nv_bfloat16 g_Woth[Dd * Dd];      // Wo^T
__device__ __nv_bfloat16 g_Wotl[Dd * Dd];
__device__ __nv_bfloat16 g_Qh[Bb * NH * Nn * DK];
__device__ __nv_bfloat16 g_Ql[Bb * NH * Nn * DK];
__device__ __nv_bfloat16 g_Kh[Bb * NH * Nn * DK];
__device__ __nv_bfloat16 g_Kl[Bb * NH * Nn * DK];
__device__ __nv_bfloat16 g_Vh[Bb * NH * Nn * DK];
__device__ __nv_bfloat16 g_Vl[Bb * NH * Nn * DK];
__device__ __nv_bfloat16 g_atth[MROWS * Dd];
__device__ __nv_bfloat16 g_attl[MROWS * Dd];

// ---------------------------------------------------------------------------
__device__ __forceinline__ void mma_bf16(float* c, const uint32_t* a, const uint32_t* b) {
    asm volatile(
        "mma.sync.aligned.m16n8k16.row.col.f32.bf16.bf16.f32 "
        "{%0,%1,%2,%3}, {%4,%5,%6,%7}, {%8,%9}, {%0,%1,%2,%3};"
        : "+f"(c[0]), "+f"(c[1]), "+f"(c[2]), "+f"(c[3])
        : "r"(a[0]), "r"(a[1]), "r"(a[2]), "r"(a[3]), "r"(b[0]), "r"(b[1]));
}

// split pair of f32 into packed bf16x2 hi + lo residue
__device__ __forceinline__ void split2(float a, float b, uint32_t& hi, uint32_t& lo) {
    __nv_bfloat16 ha = __float2bfloat16(a), hb = __float2bfloat16(b);
    __nv_bfloat16 la = __float2bfloat16(a - __bfloat162float(ha));
    __nv_bfloat16 lb = __float2bfloat16(b - __bfloat162float(hb));
    __nv_bfloat162 H(ha, hb), L(la, lb);
    hi = *(uint32_t*)&H; lo = *(uint32_t*)&L;
}

// ---------------------------------------------------------------------------
// split: f32 -> bf16 hi + lo (x input only now). float4-vectorized.
// ---------------------------------------------------------------------------
__global__ void split_kernel(const float* __restrict__ in,
                             __nv_bfloat16* __restrict__ hi,
                             __nv_bfloat16* __restrict__ lo, int n4) {
    int i = blockIdx.x * blockDim.x + threadIdx.x;
    if (i >= n4) return;
    float4 v = ((const float4*)in)[i];
    uint32_t h0, l0, h1, l1;
    split2(v.x, v.y, h0, l0);
    split2(v.z, v.w, h1, l1);
    uint32_t* H = (uint32_t*)hi;
    uint32_t* L = (uint32_t*)lo;
    H[2 * i] = h0; H[2 * i + 1] = h1;
    L[2 * i] = l0; L[2 * i + 1] = l1;
}

// transpose + split weights: W[k][n] (f32 512x512) -> T[rowoff+n][k] hi/lo
__global__ void wsplit_kernel(const float* __restrict__ W,
                              __nv_bfloat16* __restrict__ th,
                              __nv_bfloat16* __restrict__ tl, int rowoff) {
    int t = blockIdx.x * blockDim.x + threadIdx.x;
    int k = t & 511, n = t >> 9;
    float v = W[(size_t)k * Dd + n];
    __nv_bfloat16 h = __float2bfloat16(v);
    __nv_bfloat16 l = __float2bfloat16(v - __bfloat162float(h));
    th[(size_t)(rowoff + n) * Dd + k] = h;
    tl[(size_t)(rowoff + n) * Dd + k] = l;
}

// ---------------------------------------------------------------------------
// HMMA GEMM mainloop (CTA 128x64, BK=32, 8 warps 4m x 2n, warp tile 32x32).
// MODE 0: QKV - writes bf16 hi/lo head-major Q/K/V.  MODE 1: f32 row-major C.
// ---------------------------------------------------------------------------
#define LDS_K 40

template <int MODE>
__global__ __launch_bounds__(256)
void gemm_hmma(const __nv_bfloat16* __restrict__ Ah, const __nv_bfloat16* __restrict__ Al,
               const __nv_bfloat16* __restrict__ Bh, const __nv_bfloat16* __restrict__ Bl,
               float* __restrict__ Cf,
               __nv_bfloat16* __restrict__ H0, __nv_bfloat16* __restrict__ L0,
               __nv_bfloat16* __restrict__ H1, __nv_bfloat16* __restrict__ L1,
               __nv_bfloat16* __restrict__ H2, __nv_bfloat16* __restrict__ L2) {
    __shared__ __align__(16) __nv_bfloat16 sAh[128 * LDS_K];
    __shared__ __align__(16) __nv_bfloat16 sAl[128 * LDS_K];
    __shared__ __align__(16) __nv_bfloat16 sBh[64 * LDS_K];
    __shared__ __align__(16) __nv_bfloat16 sBl[64 * LDS_K];

    const int t    = threadIdx.x;
    const int wid  = t >> 5;
    const int lane = t & 31;
    const int g    = lane >> 2;
    const int tig  = lane & 3;
    const int wm   = wid & 3;
    const int wn   = wid >> 2;
    const int m0   = blockIdx.x * 128;
    const int n0   = blockIdx.y * 64;

    const uint4* gAh = (const uint4*)Ah;
    const uint4* gAl = (const uint4*)Al;
    const uint4* gBh = (const uint4*)Bh;
    const uint4* gBl = (const uint4*)Bl;

    float acc[2][4][4];
#pragma unroll
    for (int i = 0; i < 2; i++)
#pragma unroll
        for (int j = 0; j < 4; j++)
#pragma unroll
            for (int e = 0; e < 4; e++) acc[i][j][e] = 0.f;

    const uint32_t* sAh32 = (const uint32_t*)sAh;
    const uint32_t* sAl32 = (const uint32_t*)sAl;
    const uint32_t* sBh32 = (const uint32_t*)sBh;
    const uint32_t* sBl32 = (const uint32_t*)sBl;
    const int LW = LDS_K / 2;

    for (int c = 0; c < 16; c++) {
#pragma unroll
        for (int i = 0; i < 2; i++) {
            int idx = t + 256 * i;
            int r = idx >> 2, j = idx & 3;
            size_t gofs = (size_t)(m0 + r) * 64 + c * 4 + j;
            *(uint4*)(sAh + r * LDS_K + j * 8) = gAh[gofs];
            *(uint4*)(sAl + r * LDS_K + j * 8) = gAl[gofs];
        }
        {
            int r = t >> 2, j = t & 3;
            size_t gofs = (size_t)(n0 + r) * 64 + c * 4 + j;
            *(uint4*)(sBh + r * LDS_K + j * 8) = gBh[gofs];
            *(uint4*)(sBl + r * LDS_K + j * 8) = gBl[gofs];
        }
        __syncthreads();

#pragma unroll
        for (int ks = 0; ks < 2; ks++) {
            const int kw = ks * 8;
            uint32_t ah[2][4], al[2][4], bh[4][2], bl[4][2];
#pragma unroll
            for (int i = 0; i < 2; i++) {
                int row = wm * 32 + i * 16 + g;
                ah[i][0] = sAh32[row * LW + kw + tig];
                ah[i][1] = sAh32[(row + 8) * LW + kw + tig];
                ah[i][2] = sAh32[row * LW + kw + 4 + tig];
                ah[i][3] = sAh32[(row + 8) * LW + kw + 4 + tig];
                al[i][0] = sAl32[row * LW + kw + tig];
                al[i][1] = sAl32[(row + 8) * LW + kw + tig];
                al[i][2] = sAl32[row * LW + kw + 4 + tig];
                al[i][3] = sAl32[(row + 8) * LW + kw + 4 + tig];
            }
#pragma unroll
            for (int j = 0; j < 4; j++) {
                int row = wn * 32 + j * 8 + g;
                bh[j][0] = sBh32[row * LW + kw + tig];
                bh[j][1] = sBh32[row * LW + kw + 4 + tig];
                bl[j][0] = sBl32[row * LW + kw + tig];
                bl[j][1] = sBl32[row * LW + kw + 4 + tig];
            }
#pragma unroll
            for (int i = 0; i < 2; i++)
#pragma unroll
                for (int j = 0; j < 4; j++) {
                    mma_bf16(acc[i][j], ah[i], bh[j]);
                    mma_bf16(acc[i][j], ah[i], bl[j]);
                    mma_bf16(acc[i][j], al[i], bh[j]);
                }
        }
        __syncthreads();
    }

    // ---- epilogue ----
#pragma unroll
    for (int i = 0; i < 2; i++) {
#pragma unroll
        for (int j = 0; j < 4; j++) {
            int row0 = m0 + wm * 32 + i * 16 + g;
            int col  = n0 + wn * 32 + j * 8 + tig * 2;
            if (MODE == 0) {
                const int mat = n0 >> 9;
                const int cc  = col & 511;
                const int h   = cc >> 6;
                const int dk  = cc & 63;
                __nv_bfloat16* BH = (mat == 0 ? H0 : (mat == 1 ? H1 : H2));
                __nv_bfloat16* BL = (mat == 0 ? L0 : (mat == 1 ? L1 : L2));
                int bI0 = row0 >> 10, nn0 = row0 & 1023;
                int r1 = row0 + 8;
                int bI1 = r1 >> 10, nn1 = r1 & 1023;
                size_t o0 = ((size_t)((bI0 * NH + h) * Nn + nn0)) * DK + dk;
                size_t o1 = ((size_t)((bI1 * NH + h) * Nn + nn1)) * DK + dk;
                uint32_t h0, l0, h1, l1;
                split2(acc[i][j][0], acc[i][j][1], h0, l0);
                split2(acc[i][j][2], acc[i][j][3], h1, l1);
                *(uint32_t*)(BH + o0) = h0; *(uint32_t*)(BL + o0) = l0;
                *(uint32_t*)(BH + o1) = h1; *(uint32_t*)(BL + o1) = l1;
            } else {
                float* dst0 = Cf + (size_t)row0 * Dd + col;
                float* dst1 = Cf + (size_t)(row0 + 8) * Dd + col;
                *(float2*)dst0 = make_float2(acc[i][j][0], acc[i][j][1]);
                *(float2*)dst1 = make_float2(acc[i][j][2], acc[i][j][3]);
            }
        }
    }
}

// ---------------------------------------------------------------------------
// HMMA masked flash attention.
// Grid (8, 64): x = q-tile (128 rows), y = b*NH+h. 256 threads = 8 warps,
// warp w owns q rows w*16..w*16+15 (full rows -> warp-local softmax).
// Key tile 64, 16 iterations. 3-term hi/lo for both S=QK^T and PV.
// ---------------------------------------------------------------------------
#define ATT_PAD   72
#define OFF_QH    0
#define OFF_QL    18432
#define OFF_KH    36864
#define OFF_KL    46080
#define OFF_VTH   55296
#define OFF_VTL   64512
#define OFF_MASK  73728
#define ATT_SMEM  (73728 + 1024)

__global__ __launch_bounds__(256, 1)
void attn_hmma(const __nv_bfloat16* __restrict__ Qh, const __nv_bfloat16* __restrict__ Ql,
               const __nv_bfloat16* __restrict__ Kh, const __nv_bfloat16* __restrict__ Kl,
               const __nv_bfloat16* __restrict__ Vh, const __nv_bfloat16* __restrict__ Vl,
               const int* __restrict__ adj,
               __nv_bfloat16* __restrict__ Oh, __nv_bfloat16* __restrict__ Ol) {
    extern __shared__ char smraw[];
    __nv_bfloat16* sQh  = (__nv_bfloat16*)(smraw + OFF_QH);
    __nv_bfloat16* sQl  = (__nv_bfloat16*)(smraw + OFF_QL);
    __nv_bfloat16* sKh  = (__nv_bfloat16*)(smraw + OFF_KH);
    __nv_bfloat16* sKl  = (__nv_bfloat16*)(smraw + OFF_KL);
    __nv_bfloat16* sVth = (__nv_bfloat16*)(smraw + OFF_VTH);
    __nv_bfloat16* sVtl = (__nv_bfloat16*)(smraw + OFF_VTL);
    uint32_t*      smask = (uint32_t*)(smraw + OFF_MASK);

    const int t    = threadIdx.x;
    const int lane = t & 31;
    const int w    = t >> 5;
    const int g    = lane >> 2;
    const int tig  = lane & 3;
    const int bh   = blockIdx.y;
    const int bI   = bh >> 3;
    const int h    = bh & 7;
    const int q0   = blockIdx.x * 128;
    const int rw   = w * 16;

    const uint4* gQh = (const uint4*)(Qh + (size_t)bh * Nn * DK);
    const uint4* gQl = (const uint4*)(Ql + (size_t)bh * Nn * DK);
    const uint4* gKh = (const uint4*)(Kh + (size_t)bh * Nn * DK);
    const uint4* gKl = (const uint4*)(Kl + (size_t)bh * Nn * DK);
    const uint4* gVh = (const uint4*)(Vh + (size_t)bh * Nn * DK);
    const uint4* gVl = (const uint4*)(Vl + (size_t)bh * Nn * DK);
    const int* adjb  = adj + (size_t)bI * Nn * Nn;

    // ---- load Q tile (128 x 64) hi/lo ----
#pragma unroll
    for (int i = 0; i < 4; i++) {
        int idx = t + 256 * i;            // 0..1023
        int row = idx >> 3, c8 = idx & 7;
        *(uint4*)(sQh + row * ATT_PAD + c8 * 8) = gQh[(size_t)(q0 + row) * 8 + c8];
        *(uint4*)(sQl + row * ATT_PAD + c8 * 8) = gQl[(size_t)(q0 + row) * 8 + c8];
    }
    __syncthreads();

    // ---- cache Q A-fragments in registers ----
    uint32_t qh[4][4], ql[4][4];
#pragma unroll
    for (int ks = 0; ks < 4; ks++) {
        int co = ks * 16 + 2 * tig;
        qh[ks][0] = *(const uint32_t*)(sQh + (rw + g) * ATT_PAD + co);
        qh[ks][1] = *(const uint32_t*)(sQh + (rw + g + 8) * ATT_PAD + co);
        qh[ks][2] = *(const uint32_t*)(sQh + (rw + g) * ATT_PAD + co + 8);
        qh[ks][3] = *(const uint32_t*)(sQh + (rw + g + 8) * ATT_PAD + co + 8);
        ql[ks][0] = *(const uint32_t*)(sQl + (rw + g) * ATT_PAD + co);
        ql[ks][1] = *(const uint32_t*)(sQl + (rw + g + 8) * ATT_PAD + co);
        ql[ks][2] = *(const uint32_t*)(sQl + (rw + g) * ATT_PAD + co + 8);
        ql[ks][3] = *(const uint32_t*)(sQl + (rw + g + 8) * ATT_PAD + co + 8);
    }

    float m0 = -1e30f, m1 = -1e30f, l0 = 0.f, l1 = 0.f;
    float o[8][4];
#pragma unroll
    for (int j = 0; j < 8; j++)
#pragma unroll
        for (int e = 0; e < 4; e++) o[j][e] = 0.f;

    for (int kt = 0; kt < 16; kt++) {
        const int k0 = kt * 64;
        __syncthreads();
        // ---- load K tile, V tile (transposed) ----
#pragma unroll
        for (int i = 0; i < 2; i++) {
            int idx = t + 256 * i;        // 0..511
            int row = idx >> 3, c8 = idx & 7;
            size_t go = (size_t)(k0 + row) * 8 + c8;
            *(uint4*)(sKh + row * ATT_PAD + c8 * 8) = gKh[go];
            *(uint4*)(sKl + row * ATT_PAD + c8 * 8) = gKl[go];
            uint4 vh4 = gVh[go];
            uint4 vl4 = gVl[go];
            const __nv_bfloat16* pvh = (const __nv_bfloat16*)&vh4;
            const __nv_bfloat16* pvl = (const __nv_bfloat16*)&vl4;
#pragma unroll
            for (int e = 0; e < 8; e++) {
                sVth[(c8 * 8 + e) * ATT_PAD + row] = pvh[e];
                sVtl[(c8 * 8 + e) * ATT_PAD + row] = pvl[e];
            }
        }
        // ---- ballot-pack adjacency masks (warp w -> rows rw..rw+15) ----
#pragma unroll
        for (int r = 0; r < 16; r++) {
            int row = rw + r;
            const int* ar = adjb + (size_t)(q0 + row) * Nn + k0;
            uint32_t b0 = __ballot_sync(0xFFFFFFFFu, ar[lane] != 0);
            uint32_t b1 = __ballot_sync(0xFFFFFFFFu, ar[32 + lane] != 0);
            if (lane == 0) { smask[row * 2] = b0; smask[row * 2 + 1] = b1; }
        }
        __syncthreads();

        // ---- S = Q K^T (3-term hi/lo) ----
        float sacc[8][4];
#pragma unroll
        for (int j = 0; j < 8; j++)
#pragma unroll
            for (int e = 0; e < 4; e++) sacc[j][e] = 0.f;
#pragma unroll
        for (int ks = 0; ks < 4; ks++) {
            int co = ks * 16 + 2 * tig;
#pragma unroll
            for (int j = 0; j < 8; j++) {
                int rb = (j * 8 + g) * ATT_PAD;
                uint32_t kb[2], klb[2];
                kb[0]  = *(const uint32_t*)(sKh + rb + co);
                kb[1]  = *(const uint32_t*)(sKh + rb + co + 8);
                klb[0] = *(const uint32_t*)(sKl + rb + co);
                klb[1] = *(const uint32_t*)(sKl + rb + co + 8);
                mma_bf16(sacc[j], qh[ks], kb);
                mma_bf16(sacc[j], qh[ks], klb);
                mma_bf16(sacc[j], ql[ks], kb);
            }
        }

        // ---- mask + online softmax (rows g and g+8; quad shfl reduce) ----
        uint32_t M00 = smask[(rw + g) * 2],     M01 = smask[(rw + g) * 2 + 1];
        uint32_t M10 = smask[(rw + g + 8) * 2], M11 = smask[(rw + g + 8) * 2 + 1];
        float rmax0 = -1e30f, rmax1 = -1e30f;
#pragma unroll
        for (int j = 0; j < 8; j++) {
            int kb0 = j * 8 + 2 * tig;
            uint32_t w0 = (kb0 & 32) ? M01 : M00;
            uint32_t w1 = (kb0 & 32) ? M11 : M10;
            int sh = kb0 & 31;
            sacc[j][0] = ((w0 >> sh) & 1)       ? sacc[j][0] * 0.125f : -1e30f;
            sacc[j][1] = ((w0 >> (sh + 1)) & 1) ? sacc[j][1] * 0.125f : -1e30f;
            sacc[j][2] = ((w1 >> sh) & 1)       ? sacc[j][2] * 0.125f : -1e30f;
            sacc[j][3] = ((w1 >> (sh + 1)) & 1) ? sacc[j][3] * 0.125f : -1e30f;
            rmax0 = fmaxf(rmax0, fmaxf(sacc[j][0], sacc[j][1]));
            rmax1 = fmaxf(rmax1, fmaxf(sacc[j][2], sacc[j][3]));
        }
        rmax0 = fmaxf(rmax0, __shfl_xor_sync(0xFFFFFFFFu, rmax0, 1));
        rmax0 = fmaxf(rmax0, __shfl_xor_sync(0xFFFFFFFFu, rmax0, 2));
        rmax1 = fmaxf(rmax1, __shfl_xor_sync(0xFFFFFFFFu, rmax1, 1));
        rmax1 = fmaxf(rmax1, __shfl_xor_sync(0xFFFFFFFFu, rmax1, 2));
        float mn0 = fmaxf(m0, rmax0), mn1 = fmaxf(m1, rmax1);
        float al0 = __expf(m0 - mn0), al1 = __expf(m1 - mn1);
        m0 = mn0; m1 = mn1;
        float rs0 = 0.f, rs1 = 0.f;
#pragma unroll
        for (int j = 0; j < 8; j++) {
            float p0 = __expf(sacc[j][0] - mn0);
            float p1 = __expf(sacc[j][1] - mn0);
            float p2 = __expf(sacc[j][2] - mn1);
            float p3 = __expf(sacc[j][3] - mn1);
            sacc[j][0] = p0; sacc[j][1] = p1; sacc[j][2] = p2; sacc[j][3] = p3;
            rs0 += p0 + p1; rs1 += p2 + p3;
        }
        rs0 += __shfl_xor_sync(0xFFFFFFFFu, rs0, 1);
        rs0 += __shfl_xor_sync(0xFFFFFFFFu, rs0, 2);
        rs1 += __shfl_xor_sync(0xFFFFFFFFu, rs1, 1);
        rs1 += __shfl_xor_sync(0xFFFFFFFFu, rs1, 2);
        l0 = l0 * al0 + rs0; l1 = l1 * al1 + rs1;
#pragma unroll
        for (int j = 0; j < 8; j++) {
            o[j][0] *= al0; o[j][1] *= al0; o[j][2] *= al1; o[j][3] *= al1;
        }

        // ---- P (hi/lo, thread-local repack) @ V (3-term) ----
#pragma unroll
        for (int ks = 0; ks < 4; ks++) {
            uint32_t ph[4], pl[4];
            float* f0 = sacc[2 * ks];
            float* f1 = sacc[2 * ks + 1];
            split2(f0[0], f0[1], ph[0], pl[0]);
            split2(f0[2], f0[3], ph[1], pl[1]);
            split2(f1[0], f1[1], ph[2], pl[2]);
            split2(f1[2], f1[3], ph[3], pl[3]);
            int kb = ks * 16 + 2 * tig;
#pragma unroll
            for (int j = 0; j < 8; j++) {
                int rb = (j * 8 + g) * ATT_PAD;
                uint32_t vb[2], vlb[2];
                vb[0]  = *(const uint32_t*)(sVth + rb + kb);
                vb[1]  = *(const uint32_t*)(sVth + rb + kb + 8);
                vlb[0] = *(const uint32_t*)(sVtl + rb + kb);
                vlb[1] = *(const uint32_t*)(sVtl + rb + kb + 8);
                mma_bf16(o[j], ph, vb);
                mma_bf16(o[j], pl, vb);
                mma_bf16(o[j], ph, vlb);
            }
        }
    }

    // ---- epilogue: normalize, relu, hi/lo split, write [b][q][h*64+dk] ----
    float inv0 = 1.f / l0, inv1 = 1.f / l1;
    size_t row0 = (size_t)(bI * Nn + q0 + rw + g);
    size_t row1 = row0 + 8;
#pragma unroll
    for (int j = 0; j < 8; j++) {
        int col = h * 64 + j * 8 + 2 * tig;
        float v00 = fmaxf(o[j][0] * inv0, 0.f);
        float v01 = fmaxf(o[j][1] * inv0, 0.f);
        float v10 = fmaxf(o[j][2] * inv1, 0.f);
        float v11 = fmaxf(o[j][3] * inv1, 0.f);
        uint32_t h0, lo0, h1, lo1;
        split2(v00, v01, h0, lo0);
        split2(v10, v11, h1, lo1);
        *(uint32_t*)(Oh + row0 * Dd + col) = h0;
        *(uint32_t*)(Ol + row0 * Dd + col) = lo0;
        *(uint32_t*)(Oh + row1 * Dd + col) = h1;
        *(uint32_t*)(Ol + row1 * Dd + col) = lo1;
    }
}

// ---------------------------------------------------------------------------
extern "C" void kernel_launch(void* const* d_in, const int* in_sizes, int n_in,
                              void* d_out, int out_size) {
    const float* x   = (const float*)d_in[0];
    const int*   adj = (const int*)d_in[1];
    const float* Wq  = (const float*)d_in[2];
    const float* Wk  = (const float*)d_in[3];
    const float* Wv  = (const float*)d_in[4];
    const float* Wo  = (const float*)d_in[5];
    float* out = (float*)d_out;

    __nv_bfloat16 *pxh, *pxl, *pWth, *pWtl, *pWoth, *pWotl;
    __nv_bfloat16 *pQh, *pQl, *pKh, *pKl, *pVh, *pVl, *patth, *pattl;
    cudaGetSymbolAddress((void**)&pxh, g_xh);
    cudaGetSymbolAddress((void**)&pxl, g_xl);
    cudaGetSymbolAddress((void**)&pWth, g_Wth);
    cudaGetSymbolAddress((void**)&pWtl, g_Wtl);
    cudaGetSymbolAddress((void**)&pWoth, g_Woth);
    cudaGetSymbolAddress((void**)&pWotl, g_Wotl);
    cudaGetSymbolAddress((void**)&pQh, g_Qh);
    cudaGetSymbolAddress((void**)&pQl, g_Ql);
    cudaGetSymbolAddress((void**)&pKh, g_Kh);
    cudaGetSymbolAddress((void**)&pKl, g_Kl);
    cudaGetSymbolAddress((void**)&pVh, g_Vh);
    cudaGetSymbolAddress((void**)&pVl, g_Vl);
    cudaGetSymbolAddress((void**)&patth, g_atth);
    cudaGetSymbolAddress((void**)&pattl, g_attl);

    cudaFuncSetAttribute(attn_hmma, cudaFuncAttributeMaxDynamicSharedMemorySize, ATT_SMEM);

    const int n4 = MROWS * Dd / 4;

    split_kernel<<<n4 / 256, 256>>>(x, pxh, pxl, n4);
    wsplit_kernel<<<1024, 256>>>(Wq, pWth, pWtl, 0);
    wsplit_kernel<<<1024, 256>>>(Wk, pWth, pWtl, 512);
    wsplit_kernel<<<1024, 256>>>(Wv, pWth, pWtl, 1024);
    wsplit_kernel<<<1024, 256>>>(Wo, pWoth, pWotl, 0);

    gemm_hmma<0><<<dim3(MROWS / 128, 1536 / 64), 256>>>(
        pxh, pxl, pWth, pWtl, nullptr, pQh, pQl, pKh, pKl, pVh, pVl);

    attn_hmma<<<dim3(Nn / 128, Bb * NH), 256, ATT_SMEM>>>(
        pQh, pQl, pKh, pKl, pVh, pVl, adj, patth, pattl);

    gemm_hmma<1><<<dim3(MROWS / 128, Dd / 64), 256>>>(
        patth, pattl, pWoth, pWotl, out,
        nullptr, nullptr, nullptr, nullptr, nullptr, nullptr);
}

// round 7
// speedup vs baseline: 2.3380x; 1.1729x over previous
#include <cuda_runtime.h>
#include <cuda_bf16.h>
#include <cstdint>
#include <cstddef>

// ---------------------------------------------------------------------------
// GATLayer: out = relu( MHA_masked(x; Wq,Wk,Wv, adj) ) @ Wo
// B=8, N=1024, D=512, NH=8, DK=64
// Round 5: precomputed adjacency bitmasks (1 bit/edge, built once) and
// V stored pre-transposed [bh][dk][key] by the QKV GEMM epilogue.
// All matmuls on HMMA bf16 hi/lo x3 (fp32-grade accuracy).
// ---------------------------------------------------------------------------

#define Bb   8
#define Nn   1024
#define Dd   512
#define NH   8
#define DK   64
#define MROWS (Bb * Nn)          // 8192

// ---------------- scratch ----------------
__device__ __nv_bfloat16 g_xh[MROWS * Dd];
__device__ __nv_bfloat16 g_xl[MROWS * Dd];
__device__ __nv_bfloat16 g_Wth[3 * Dd * Dd];
__device__ __nv_bfloat16 g_Wtl[3 * Dd * Dd];
__device__ __nv_bfloat16 g_Woth[Dd * Dd];
__device__ __nv_bfloat16 g_Wotl[Dd * Dd];
__device__ __nv_bfloat16 g_Qh[Bb * NH * Nn * DK];
__device__ __nv_bfloat16 g_Ql[Bb * NH * Nn * DK];
__device__ __nv_bfloat16 g_Kh[Bb * NH * Nn * DK];
__device__ __nv_bfloat16 g_Kl[Bb * NH * Nn * DK];
__device__ __nv_bfloat16 g_VTh[Bb * NH * DK * Nn];   // [bh][dk][key]
__device__ __nv_bfloat16 g_VTl[Bb * NH * DK * Nn];
__device__ __nv_bfloat16 g_atth[MROWS * Dd];
__device__ __nv_bfloat16 g_attl[MROWS * Dd];
__device__ uint32_t g_mask[Bb * Nn * 32];            // packed adj bits

// ---------------------------------------------------------------------------
__device__ __forceinline__ void mma_bf16(float* c, const uint32_t* a, const uint32_t* b) {
    asm volatile(
        "mma.sync.aligned.m16n8k16.row.col.f32.bf16.bf16.f32 "
        "{%0,%1,%2,%3}, {%4,%5,%6,%7}, {%8,%9}, {%0,%1,%2,%3};"
        : "+f"(c[0]), "+f"(c[1]), "+f"(c[2]), "+f"(c[3])
        : "r"(a[0]), "r"(a[1]), "r"(a[2]), "r"(a[3]), "r"(b[0]), "r"(b[1]));
}

__device__ __forceinline__ void split2(float a, float b, uint32_t& hi, uint32_t& lo) {
    __nv_bfloat16 ha = __float2bfloat16(a), hb = __float2bfloat16(b);
    __nv_bfloat16 la = __float2bfloat16(a - __bfloat162float(ha));
    __nv_bfloat16 lb = __float2bfloat16(b - __bfloat162float(hb));
    __nv_bfloat162 H(ha, hb), L(la, lb);
    hi = *(uint32_t*)&H; lo = *(uint32_t*)&L;
}
__device__ __forceinline__ void split1(float v, __nv_bfloat16& h, __nv_bfloat16& l) {
    h = __float2bfloat16(v);
    l = __float2bfloat16(v - __bfloat162float(h));
}

// ---------------------------------------------------------------------------
__global__ void split_kernel(const float* __restrict__ in,
                             __nv_bfloat16* __restrict__ hi,
                             __nv_bfloat16* __restrict__ lo, int n4) {
    int i = blockIdx.x * blockDim.x + threadIdx.x;
    if (i >= n4) return;
    float4 v = ((const float4*)in)[i];
    uint32_t h0, l0, h1, l1;
    split2(v.x, v.y, h0, l0);
    split2(v.z, v.w, h1, l1);
    uint32_t* H = (uint32_t*)hi;
    uint32_t* L = (uint32_t*)lo;
    H[2 * i] = h0; H[2 * i + 1] = h1;
    L[2 * i] = l0; L[2 * i + 1] = l1;
}

__global__ void wsplit_kernel(const float* __restrict__ W,
                              __nv_bfloat16* __restrict__ th,
                              __nv_bfloat16* __restrict__ tl, int rowoff) {
    int t = blockIdx.x * blockDim.x + threadIdx.x;
    int k = t & 511, n = t >> 9;
    float v = W[(size_t)k * Dd + n];
    __nv_bfloat16 h, l;
    split1(v, h, l);
    th[(size_t)(rowoff + n) * Dd + k] = h;
    tl[(size_t)(rowoff + n) * Dd + k] = l;
}

// pack adj [8][1024][1024] int32 -> bitmask [8*1024][32] (warp per row)
__global__ void adjmask_kernel(const int* __restrict__ adj,
                               uint32_t* __restrict__ mask) {
    int row  = (blockIdx.x * blockDim.x + threadIdx.x) >> 5;
    int lane = threadIdx.x & 31;
    if (row >= Bb * Nn) return;
    const int* ar = adj + (size_t)row * Nn;
    uint32_t* mr = mask + (size_t)row * 32;
#pragma unroll
    for (int j = 0; j < 32; j++) {
        uint32_t b = __ballot_sync(0xFFFFFFFFu, ar[j * 32 + lane] != 0);
        if (lane == 0) mr[j] = b;
    }
}

// ---------------------------------------------------------------------------
// HMMA GEMM (CTA 128x64, BK=32, 8 warps 4m x 2n, warp tile 32x32).
// MODE 0: QKV - Q/K head-major hi/lo; V written TRANSPOSED [bh][dk][key].
// MODE 1: f32 row-major C.
// ---------------------------------------------------------------------------
#define LDS_K 40

template <int MODE>
__global__ __launch_bounds__(256)
void gemm_hmma(const __nv_bfloat16* __restrict__ Ah, const __nv_bfloat16* __restrict__ Al,
               const __nv_bfloat16* __restrict__ Bh, const __nv_bfloat16* __restrict__ Bl,
               float* __restrict__ Cf,
               __nv_bfloat16* __restrict__ H0, __nv_bfloat16* __restrict__ L0,
               __nv_bfloat16* __restrict__ H1, __nv_bfloat16* __restrict__ L1,
               __nv_bfloat16* __restrict__ H2, __nv_bfloat16* __restrict__ L2) {
    __shared__ __align__(16) __nv_bfloat16 sAh[128 * LDS_K];
    __shared__ __align__(16) __nv_bfloat16 sAl[128 * LDS_K];
    __shared__ __align__(16) __nv_bfloat16 sBh[64 * LDS_K];
    __shared__ __align__(16) __nv_bfloat16 sBl[64 * LDS_K];

    const int t    = threadIdx.x;
    const int wid  = t >> 5;
    const int lane = t & 31;
    const int g    = lane >> 2;
    const int tig  = lane & 3;
    const int wm   = wid & 3;
    const int wn   = wid >> 2;
    const int m0   = blockIdx.x * 128;
    const int n0   = blockIdx.y * 64;

    const uint4* gAh = (const uint4*)Ah;
    const uint4* gAl = (const uint4*)Al;
    const uint4* gBh = (const uint4*)Bh;
    const uint4* gBl = (const uint4*)Bl;

    float acc[2][4][4];
#pragma unroll
    for (int i = 0; i < 2; i++)
#pragma unroll
        for (int j = 0; j < 4; j++)
#pragma unroll
            for (int e = 0; e < 4; e++) acc[i][j][e] = 0.f;

    const uint32_t* sAh32 = (const uint32_t*)sAh;
    const uint32_t* sAl32 = (const uint32_t*)sAl;
    const uint32_t* sBh32 = (const uint32_t*)sBh;
    const uint32_t* sBl32 = (const uint32_t*)sBl;
    const int LW = LDS_K / 2;

    for (int c = 0; c < 16; c++) {
#pragma unroll
        for (int i = 0; i < 2; i++) {
            int idx = t + 256 * i;
            int r = idx >> 2, j = idx & 3;
            size_t gofs = (size_t)(m0 + r) * 64 + c * 4 + j;
            *(uint4*)(sAh + r * LDS_K + j * 8) = gAh[gofs];
            *(uint4*)(sAl + r * LDS_K + j * 8) = gAl[gofs];
        }
        {
            int r = t >> 2, j = t & 3;
            size_t gofs = (size_t)(n0 + r) * 64 + c * 4 + j;
            *(uint4*)(sBh + r * LDS_K + j * 8) = gBh[gofs];
            *(uint4*)(sBl + r * LDS_K + j * 8) = gBl[gofs];
        }
        __syncthreads();

#pragma unroll
        for (int ks = 0; ks < 2; ks++) {
            const int kw = ks * 8;
            uint32_t ah[2][4], al[2][4], bh[4][2], bl[4][2];
#pragma unroll
            for (int i = 0; i < 2; i++) {
                int row = wm * 32 + i * 16 + g;
                ah[i][0] = sAh32[row * LW + kw + tig];
                ah[i][1] = sAh32[(row + 8) * LW + kw + tig];
                ah[i][2] = sAh32[row * LW + kw + 4 + tig];
                ah[i][3] = sAh32[(row + 8) * LW + kw + 4 + tig];
                al[i][0] = sAl32[row * LW + kw + tig];
                al[i][1] = sAl32[(row + 8) * LW + kw + tig];
                al[i][2] = sAl32[row * LW + kw + 4 + tig];
                al[i][3] = sAl32[(row + 8) * LW + kw + 4 + tig];
            }
#pragma unroll
            for (int j = 0; j < 4; j++) {
                int row = wn * 32 + j * 8 + g;
                bh[j][0] = sBh32[row * LW + kw + tig];
                bh[j][1] = sBh32[row * LW + kw + 4 + tig];
                bl[j][0] = sBl32[row * LW + kw + tig];
                bl[j][1] = sBl32[row * LW + kw + 4 + tig];
            }
#pragma unroll
            for (int i = 0; i < 2; i++)
#pragma unroll
                for (int j = 0; j < 4; j++) {
                    mma_bf16(acc[i][j], ah[i], bh[j]);
                    mma_bf16(acc[i][j], ah[i], bl[j]);
                    mma_bf16(acc[i][j], al[i], bh[j]);
                }
        }
        __syncthreads();
    }

    // ---- epilogue ----
#pragma unroll
    for (int i = 0; i < 2; i++) {
#pragma unroll
        for (int j = 0; j < 4; j++) {
            int row0 = m0 + wm * 32 + i * 16 + g;
            int col  = n0 + wn * 32 + j * 8 + tig * 2;
            if (MODE == 0) {
                const int mat = n0 >> 9;
                const int cc  = col & 511;
                const int h   = cc >> 6;
                const int dk  = cc & 63;
                const int bI  = row0 >> 10;        // same for row0 and row0+8
                const int nn0 = row0 & 1023;
                const int nn1 = (row0 + 8) & 1023;
                if (mat == 2) {
                    // V transposed: [bh][dk][key]
                    size_t vb = (size_t)((bI * NH + h) * DK + dk) * Nn;
                    __nv_bfloat16 hh, ll;
                    split1(acc[i][j][0], hh, ll); H2[vb + nn0] = hh; L2[vb + nn0] = ll;
                    split1(acc[i][j][2], hh, ll); H2[vb + nn1] = hh; L2[vb + nn1] = ll;
                    split1(acc[i][j][1], hh, ll); H2[vb + Nn + nn0] = hh; L2[vb + Nn + nn0] = ll;
                    split1(acc[i][j][3], hh, ll); H2[vb + Nn + nn1] = hh; L2[vb + Nn + nn1] = ll;
                } else {
                    __nv_bfloat16* BH = (mat == 0 ? H0 : H1);
                    __nv_bfloat16* BL = (mat == 0 ? L0 : L1);
                    size_t o0 = ((size_t)((bI * NH + h) * Nn + nn0)) * DK + dk;
                    size_t o1 = ((size_t)((bI * NH + h) * Nn + nn1)) * DK + dk;
                    uint32_t h0, l0, h1, l1;
                    split2(acc[i][j][0], acc[i][j][1], h0, l0);
                    split2(acc[i][j][2], acc[i][j][3], h1, l1);
                    *(uint32_t*)(BH + o0) = h0; *(uint32_t*)(BL + o0) = l0;
                    *(uint32_t*)(BH + o1) = h1; *(uint32_t*)(BL + o1) = l1;
                }
            } else {
                float* dst0 = Cf + (size_t)row0 * Dd + col;
                float* dst1 = Cf + (size_t)(row0 + 8) * Dd + col;
                *(float2*)dst0 = make_float2(acc[i][j][0], acc[i][j][1]);
                *(float2*)dst1 = make_float2(acc[i][j][2], acc[i][j][3]);
            }
        }
    }
}

// ---------------------------------------------------------------------------
// HMMA masked flash attention. Grid (8, 64), 256 thr = 8 warps, warp owns
// 16 q rows. Key tile 64 x 16 iters. Masks from precomputed bitfield.
// V pre-transposed in global -> plain vectorized smem copy.
// ---------------------------------------------------------------------------
#define ATT_PAD   72
#define OFF_QH    0
#define OFF_QL    18432
#define OFF_KH    36864
#define OFF_KL    46080
#define OFF_VTH   55296
#define OFF_VTL   64512
#define ATT_SMEM  73728

__global__ __launch_bounds__(256, 1)
void attn_hmma(const __nv_bfloat16* __restrict__ Qh, const __nv_bfloat16* __restrict__ Ql,
               const __nv_bfloat16* __restrict__ Kh, const __nv_bfloat16* __restrict__ Kl,
               const __nv_bfloat16* __restrict__ VTh, const __nv_bfloat16* __restrict__ VTl,
               const uint32_t* __restrict__ mask,
               __nv_bfloat16* __restrict__ Oh, __nv_bfloat16* __restrict__ Ol) {
    extern __shared__ char smraw[];
    __nv_bfloat16* sQh  = (__nv_bfloat16*)(smraw + OFF_QH);
    __nv_bfloat16* sQl  = (__nv_bfloat16*)(smraw + OFF_QL);
    __nv_bfloat16* sKh  = (__nv_bfloat16*)(smraw + OFF_KH);
    __nv_bfloat16* sKl  = (__nv_bfloat16*)(smraw + OFF_KL);
    __nv_bfloat16* sVth = (__nv_bfloat16*)(smraw + OFF_VTH);
    __nv_bfloat16* sVtl = (__nv_bfloat16*)(smraw + OFF_VTL);

    const int t    = threadIdx.x;
    const int lane = t & 31;
    const int w    = t >> 5;
    const int g    = lane >> 2;
    const int tig  = lane & 3;
    const int bh   = blockIdx.y;
    const int bI   = bh >> 3;
    const int h    = bh & 7;
    const int q0   = blockIdx.x * 128;
    const int rw   = w * 16;

    const uint4* gQh  = (const uint4*)(Qh + (size_t)bh * Nn * DK);
    const uint4* gQl  = (const uint4*)(Ql + (size_t)bh * Nn * DK);
    const uint4* gKh  = (const uint4*)(Kh + (size_t)bh * Nn * DK);
    const uint4* gKl  = (const uint4*)(Kl + (size_t)bh * Nn * DK);
    const uint4* gVTh = (const uint4*)(VTh + (size_t)bh * DK * Nn);
    const uint4* gVTl = (const uint4*)(VTl + (size_t)bh * DK * Nn);
    const uint32_t* mrow0 = mask + ((size_t)(bI * Nn + q0 + rw + g)) * 32;
    const uint32_t* mrow1 = mrow0 + 8 * 32;

    // ---- load Q tile (128 x 64) hi/lo ----
#pragma unroll
    for (int i = 0; i < 4; i++) {
        int idx = t + 256 * i;
        int row = idx >> 3, c8 = idx & 7;
        *(uint4*)(sQh + row * ATT_PAD + c8 * 8) = gQh[(size_t)(q0 + row) * 8 + c8];
        *(uint4*)(sQl + row * ATT_PAD + c8 * 8) = gQl[(size_t)(q0 + row) * 8 + c8];
    }
    __syncthreads();

    // ---- cache Q A-fragments ----
    uint32_t qh[4][4], ql[4][4];
#pragma unroll
    for (int ks = 0; ks < 4; ks++) {
        int co = ks * 16 + 2 * tig;
        qh[ks][0] = *(const uint32_t*)(sQh + (rw + g) * ATT_PAD + co);
        qh[ks][1] = *(const uint32_t*)(sQh + (rw + g + 8) * ATT_PAD + co);
        qh[ks][2] = *(const uint32_t*)(sQh + (rw + g) * ATT_PAD + co + 8);
        qh[ks][3] = *(const uint32_t*)(sQh + (rw + g + 8) * ATT_PAD + co + 8);
        ql[ks][0] = *(const uint32_t*)(sQl + (rw + g) * ATT_PAD + co);
        ql[ks][1] = *(const uint32_t*)(sQl + (rw + g + 8) * ATT_PAD + co);
        ql[ks][2] = *(const uint32_t*)(sQl + (rw + g) * ATT_PAD + co + 8);
        ql[ks][3] = *(const uint32_t*)(sQl + (rw + g + 8) * ATT_PAD + co + 8);
    }

    float m0 = -1e30f, m1 = -1e30f, l0 = 0.f, l1 = 0.f;
    float o[8][4];
#pragma unroll
    for (int j = 0; j < 8; j++)
#pragma unroll
        for (int e = 0; e < 4; e++) o[j][e] = 0.f;

    for (int kt = 0; kt < 16; kt++) {
        const int k0 = kt * 64;
        __syncthreads();
        // ---- load K tile + VT tile (both plain vectorized copies) ----
#pragma unroll
        for (int i = 0; i < 2; i++) {
            int idx = t + 256 * i;        // 0..511
            int row = idx >> 3, c8 = idx & 7;
            size_t gk = (size_t)(k0 + row) * 8 + c8;
            *(uint4*)(sKh + row * ATT_PAD + c8 * 8) = gKh[gk];
            *(uint4*)(sKl + row * ATT_PAD + c8 * 8) = gKl[gk];
            size_t gv = (size_t)row * 128 + (k0 >> 3) + c8;   // VT row=dk
            *(uint4*)(sVth + row * ATT_PAD + c8 * 8) = gVTh[gv];
            *(uint4*)(sVtl + row * ATT_PAD + c8 * 8) = gVTl[gv];
        }
        __syncthreads();

        // ---- S = Q K^T (3-term hi/lo) ----
        float sacc[8][4];
#pragma unroll
        for (int j = 0; j < 8; j++)
#pragma unroll
            for (int e = 0; e < 4; e++) sacc[j][e] = 0.f;
#pragma unroll
        for (int ks = 0; ks < 4; ks++) {
            int co = ks * 16 + 2 * tig;
#pragma unroll
            for (int j = 0; j < 8; j++) {
                int rb = (j * 8 + g) * ATT_PAD;
                uint32_t kb[2], klb[2];
                kb[0]  = *(const uint32_t*)(sKh + rb + co);
                kb[1]  = *(const uint32_t*)(sKh + rb + co + 8);
                klb[0] = *(const uint32_t*)(sKl + rb + co);
                klb[1] = *(const uint32_t*)(sKl + rb + co + 8);
                mma_bf16(sacc[j], qh[ks], kb);
                mma_bf16(sacc[j], qh[ks], klb);
                mma_bf16(sacc[j], ql[ks], kb);
            }
        }

        // ---- mask (precomputed bits) + online softmax ----
        uint32_t M00 = mrow0[2 * kt], M01 = mrow0[2 * kt + 1];
        uint32_t M10 = mrow1[2 * kt], M11 = mrow1[2 * kt + 1];
        float rmax0 = -1e30f, rmax1 = -1e30f;
#pragma unroll
        for (int j = 0; j < 8; j++) {
            int kb0 = j * 8 + 2 * tig;
            uint32_t w0 = (kb0 & 32) ? M01 : M00;
            uint32_t w1 = (kb0 & 32) ? M11 : M10;
            int sh = kb0 & 31;
            sacc[j][0] = ((w0 >> sh) & 1)       ? sacc[j][0] * 0.125f : -1e30f;
            sacc[j][1] = ((w0 >> (sh + 1)) & 1) ? sacc[j][1] * 0.125f : -1e30f;
            sacc[j][2] = ((w1 >> sh) & 1)       ? sacc[j][2] * 0.125f : -1e30f;
            sacc[j][3] = ((w1 >> (sh + 1)) & 1) ? sacc[j][3] * 0.125f : -1e30f;
            rmax0 = fmaxf(rmax0, fmaxf(sacc[j][0], sacc[j][1]));
            rmax1 = fmaxf(rmax1, fmaxf(sacc[j][2], sacc[j][3]));
        }
        rmax0 = fmaxf(rmax0, __shfl_xor_sync(0xFFFFFFFFu, rmax0, 1));
        rmax0 = fmaxf(rmax0, __shfl_xor_sync(0xFFFFFFFFu, rmax0, 2));
        rmax1 = fmaxf(rmax1, __shfl_xor_sync(0xFFFFFFFFu, rmax1, 1));
        rmax1 = fmaxf(rmax1, __shfl_xor_sync(0xFFFFFFFFu, rmax1, 2));
        float mn0 = fmaxf(m0, rmax0), mn1 = fmaxf(m1, rmax1);
        float al0 = __expf(m0 - mn0), al1 = __expf(m1 - mn1);
        m0 = mn0; m1 = mn1;
        float rs0 = 0.f, rs1 = 0.f;
#pragma unroll
        for (int j = 0; j < 8; j++) {
            float p0 = __expf(sacc[j][0] - mn0);
            float p1 = __expf(sacc[j][1] - mn0);
            float p2 = __expf(sacc[j][2] - mn1);
            float p3 = __expf(sacc[j][3] - mn1);
            sacc[j][0] = p0; sacc[j][1] = p1; sacc[j][2] = p2; sacc[j][3] = p3;
            rs0 += p0 + p1; rs1 += p2 + p3;
        }
        rs0 += __shfl_xor_sync(0xFFFFFFFFu, rs0, 1);
        rs0 += __shfl_xor_sync(0xFFFFFFFFu, rs0, 2);
        rs1 += __shfl_xor_sync(0xFFFFFFFFu, rs1, 1);
        rs1 += __shfl_xor_sync(0xFFFFFFFFu, rs1, 2);
        l0 = l0 * al0 + rs0; l1 = l1 * al1 + rs1;
#pragma unroll
        for (int j = 0; j < 8; j++) {
            o[j][0] *= al0; o[j][1] *= al0; o[j][2] *= al1; o[j][3] *= al1;
        }

        // ---- P (hi/lo thread-local repack) @ V (3-term) ----
#pragma unroll
        for (int ks = 0; ks < 4; ks++) {
            uint32_t ph[4], pl[4];
            float* f0 = sacc[2 * ks];
            float* f1 = sacc[2 * ks + 1];
            split2(f0[0], f0[1], ph[0], pl[0]);
            split2(f0[2], f0[3], ph[1], pl[1]);
            split2(f1[0], f1[1], ph[2], pl[2]);
            split2(f1[2], f1[3], ph[3], pl[3]);
            int kb = ks * 16 + 2 * tig;
#pragma unroll
            for (int j = 0; j < 8; j++) {
                int rb = (j * 8 + g) * ATT_PAD;
                uint32_t vb[2], vlb[2];
                vb[0]  = *(const uint32_t*)(sVth + rb + kb);
                vb[1]  = *(const uint32_t*)(sVth + rb + kb + 8);
                vlb[0] = *(const uint32_t*)(sVtl + rb + kb);
                vlb[1] = *(const uint32_t*)(sVtl + rb + kb + 8);
                mma_bf16(o[j], ph, vb);
                mma_bf16(o[j], pl, vb);
                mma_bf16(o[j], ph, vlb);
            }
        }
    }

    // ---- epilogue: normalize, relu, hi/lo split, write [b][q][h*64+dk] ----
    float inv0 = 1.f / l0, inv1 = 1.f / l1;
    size_t row0 = (size_t)(bI * Nn + q0 + rw + g);
    size_t row1 = row0 + 8;
#pragma unroll
    for (int j = 0; j < 8; j++) {
        int col = h * 64 + j * 8 + 2 * tig;
        float v00 = fmaxf(o[j][0] * inv0, 0.f);
        float v01 = fmaxf(o[j][1] * inv0, 0.f);
        float v10 = fmaxf(o[j][2] * inv1, 0.f);
        float v11 = fmaxf(o[j][3] * inv1, 0.f);
        uint32_t h0, lo0, h1, lo1;
        split2(v00, v01, h0, lo0);
        split2(v10, v11, h1, lo1);
        *(uint32_t*)(Oh + row0 * Dd + col) = h0;
        *(uint32_t*)(Ol + row0 * Dd + col) = lo0;
        *(uint32_t*)(Oh + row1 * Dd + col) = h1;
        *(uint32_t*)(Ol + row1 * Dd + col) = lo1;
    }
}

// ---------------------------------------------------------------------------
extern "C" void kernel_launch(void* const* d_in, const int* in_sizes, int n_in,
                              void* d_out, int out_size) {
    const float* x   = (const float*)d_in[0];
    const int*   adj = (const int*)d_in[1];
    const float* Wq  = (const float*)d_in[2];
    const float* Wk  = (const float*)d_in[3];
    const float* Wv  = (const float*)d_in[4];
    const float* Wo  = (const float*)d_in[5];
    float* out = (float*)d_out;

    __nv_bfloat16 *pxh, *pxl, *pWth, *pWtl, *pWoth, *pWotl;
    __nv_bfloat16 *pQh, *pQl, *pKh, *pKl, *pVTh, *pVTl, *patth, *pattl;
    uint32_t* pmask;
    cudaGetSymbolAddress((void**)&pxh, g_xh);
    cudaGetSymbolAddress((void**)&pxl, g_xl);
    cudaGetSymbolAddress((void**)&pWth, g_Wth);
    cudaGetSymbolAddress((void**)&pWtl, g_Wtl);
    cudaGetSymbolAddress((void**)&pWoth, g_Woth);
    cudaGetSymbolAddress((void**)&pWotl, g_Wotl);
    cudaGetSymbolAddress((void**)&pQh, g_Qh);
    cudaGetSymbolAddress((void**)&pQl, g_Ql);
    cudaGetSymbolAddress((void**)&pKh, g_Kh);
    cudaGetSymbolAddress((void**)&pKl, g_Kl);
    cudaGetSymbolAddress((void**)&pVTh, g_VTh);
    cudaGetSymbolAddress((void**)&pVTl, g_VTl);
    cudaGetSymbolAddress((void**)&patth, g_atth);
    cudaGetSymbolAddress((void**)&pattl, g_attl);
    cudaGetSymbolAddress((void**)&pmask, g_mask);

    cudaFuncSetAttribute(attn_hmma, cudaFuncAttributeMaxDynamicSharedMemorySize, ATT_SMEM);

    const int n4 = MROWS * Dd / 4;

    split_kernel<<<n4 / 256, 256>>>(x, pxh, pxl, n4);
    wsplit_kernel<<<1024, 256>>>(Wq, pWth, pWtl, 0);
    wsplit_kernel<<<1024, 256>>>(Wk, pWth, pWtl, 512);
    wsplit_kernel<<<1024, 256>>>(Wv, pWth, pWtl, 1024);
    wsplit_kernel<<<1024, 256>>>(Wo, pWoth, pWotl, 0);
    adjmask_kernel<<<(MROWS * 32) / 256, 256>>>(adj, pmask);

    gemm_hmma<0><<<dim3(MROWS / 128, 1536 / 64), 256>>>(
        pxh, pxl, pWth, pWtl, nullptr, pQh, pQl, pKh, pKl, pVTh, pVTl);

    attn_hmma<<<dim3(Nn / 128, Bb * NH), 256, ATT_SMEM>>>(
        pQh, pQl, pKh, pKl, pVTh, pVTl, pmask, patth, pattl);

    gemm_hmma<1><<<dim3(MROWS / 128, Dd / 64), 256>>>(
        patth, pattl, pWoth, pWotl, out,
        nullptr, nullptr, nullptr, nullptr, nullptr, nullptr);
}

// round 8
// speedup vs baseline: 2.5651x; 1.0971x over previous
#include <cuda_runtime.h>
#include <cuda_bf16.h>
#include <cstdint>
#include <cstddef>

// ---------------------------------------------------------------------------
// GATLayer: out = relu( MHA_masked(x; Wq,Wk,Wv, adj) ) @ Wo
// B=8, N=1024, D=512, NH=8, DK=64
// Round 7: cp.async double-buffered pipelines in GEMM and attention.
// Attention: Q fragments straight from global (no Q smem), K/V 2-stage.
// All matmuls HMMA bf16 hi/lo x3; precomputed adj bitmasks; V pre-transposed.
// ---------------------------------------------------------------------------

#define Bb   8
#define Nn   1024
#define Dd   512
#define NH   8
#define DK   64
#define MROWS (Bb * Nn)          // 8192

// ---------------- scratch ----------------
__device__ __nv_bfloat16 g_xh[MROWS * Dd];
__device__ __nv_bfloat16 g_xl[MROWS * Dd];
__device__ __nv_bfloat16 g_Wth[3 * Dd * Dd];
__device__ __nv_bfloat16 g_Wtl[3 * Dd * Dd];
__device__ __nv_bfloat16 g_Woth[Dd * Dd];
__device__ __nv_bfloat16 g_Wotl[Dd * Dd];
__device__ __nv_bfloat16 g_Qh[Bb * NH * Nn * DK];
__device__ __nv_bfloat16 g_Ql[Bb * NH * Nn * DK];
__device__ __nv_bfloat16 g_Kh[Bb * NH * Nn * DK];
__device__ __nv_bfloat16 g_Kl[Bb * NH * Nn * DK];
__device__ __nv_bfloat16 g_VTh[Bb * NH * DK * Nn];   // [bh][dk][key]
__device__ __nv_bfloat16 g_VTl[Bb * NH * DK * Nn];
__device__ __nv_bfloat16 g_atth[MROWS * Dd];
__device__ __nv_bfloat16 g_attl[MROWS * Dd];
__device__ uint32_t g_mask[Bb * Nn * 32];            // packed adj bits

// ---------------------------------------------------------------------------
__device__ __forceinline__ void mma_bf16(float* c, const uint32_t* a, const uint32_t* b) {
    asm volatile(
        "mma.sync.aligned.m16n8k16.row.col.f32.bf16.bf16.f32 "
        "{%0,%1,%2,%3}, {%4,%5,%6,%7}, {%8,%9}, {%0,%1,%2,%3};"
        : "+f"(c[0]), "+f"(c[1]), "+f"(c[2]), "+f"(c[3])
        : "r"(a[0]), "r"(a[1]), "r"(a[2]), "r"(a[3]), "r"(b[0]), "r"(b[1]));
}

__device__ __forceinline__ void cp_async16(void* smem_dst, const void* gsrc) {
    uint32_t s = (uint32_t)__cvta_generic_to_shared(smem_dst);
    asm volatile("cp.async.cg.shared.global [%0], [%1], 16;" :: "r"(s), "l"(gsrc));
}
#define CP_COMMIT() asm volatile("cp.async.commit_group;" ::: "memory")
#define CP_WAIT1()  asm volatile("cp.async.wait_group 1;" ::: "memory")

__device__ __forceinline__ void split2(float a, float b, uint32_t& hi, uint32_t& lo) {
    __nv_bfloat16 ha = __float2bfloat16(a), hb = __float2bfloat16(b);
    __nv_bfloat16 la = __float2bfloat16(a - __bfloat162float(ha));
    __nv_bfloat16 lb = __float2bfloat16(b - __bfloat162float(hb));
    __nv_bfloat162 H(ha, hb), L(la, lb);
    hi = *(uint32_t*)&H; lo = *(uint32_t*)&L;
}
__device__ __forceinline__ void split1(float v, __nv_bfloat16& h, __nv_bfloat16& l) {
    h = __float2bfloat16(v);
    l = __float2bfloat16(v - __bfloat162float(h));
}

// ---------------------------------------------------------------------------
__global__ void split_kernel(const float* __restrict__ in,
                             __nv_bfloat16* __restrict__ hi,
                             __nv_bfloat16* __restrict__ lo, int n4) {
    int i = blockIdx.x * blockDim.x + threadIdx.x;
    if (i >= n4) return;
    float4 v = ((const float4*)in)[i];
    uint32_t h0, l0, h1, l1;
    split2(v.x, v.y, h0, l0);
    split2(v.z, v.w, h1, l1);
    uint32_t* H = (uint32_t*)hi;
    uint32_t* L = (uint32_t*)lo;
    H[2 * i] = h0; H[2 * i + 1] = h1;
    L[2 * i] = l0; L[2 * i + 1] = l1;
}

__global__ void wsplit_kernel(const float* __restrict__ W,
                              __nv_bfloat16* __restrict__ th,
                              __nv_bfloat16* __restrict__ tl, int rowoff) {
    int t = blockIdx.x * blockDim.x + threadIdx.x;
    int k = t & 511, n = t >> 9;
    float v = W[(size_t)k * Dd + n];
    __nv_bfloat16 h, l;
    split1(v, h, l);
    th[(size_t)(rowoff + n) * Dd + k] = h;
    tl[(size_t)(rowoff + n) * Dd + k] = l;
}

// pack adj [8][1024][1024] int32 -> bitmask [8*1024][32] (warp per row)
__global__ void adjmask_kernel(const int* __restrict__ adj,
                               uint32_t* __restrict__ mask) {
    int row  = (blockIdx.x * blockDim.x + threadIdx.x) >> 5;
    int lane = threadIdx.x & 31;
    if (row >= Bb * Nn) return;
    const int* ar = adj + (size_t)row * Nn;
    uint32_t* mr = mask + (size_t)row * 32;
#pragma unroll
    for (int j = 0; j < 32; j++) {
        uint32_t b = __ballot_sync(0xFFFFFFFFu, ar[j * 32 + lane] != 0);
        if (lane == 0) mr[j] = b;
    }
}

// ---------------------------------------------------------------------------
// HMMA GEMM (CTA 128x64, BK=32, 8 warps 4m x 2n), cp.async double-buffered.
// MODE 0: QKV - Q/K head-major hi/lo; V TRANSPOSED [bh][dk][key].
// MODE 1: f32 row-major C.
// ---------------------------------------------------------------------------
#define LDS_K     40
#define GST_AH    0                      // per-stage offsets (bytes)
#define GST_AL    10240
#define GST_BH    20480
#define GST_BL    25600
#define GST_SIZE  30720
#define GEMM_SMEM (2 * GST_SIZE)         // 61440

template <int MODE>
__global__ __launch_bounds__(256)
void gemm_hmma(const __nv_bfloat16* __restrict__ Ah, const __nv_bfloat16* __restrict__ Al,
               const __nv_bfloat16* __restrict__ Bh, const __nv_bfloat16* __restrict__ Bl,
               float* __restrict__ Cf,
               __nv_bfloat16* __restrict__ H0, __nv_bfloat16* __restrict__ L0,
               __nv_bfloat16* __restrict__ H1, __nv_bfloat16* __restrict__ L1,
               __nv_bfloat16* __restrict__ H2, __nv_bfloat16* __restrict__ L2) {
    extern __shared__ char sm[];

    const int t    = threadIdx.x;
    const int wid  = t >> 5;
    const int lane = t & 31;
    const int g    = lane >> 2;
    const int tig  = lane & 3;
    const int wm   = wid & 3;
    const int wn   = wid >> 2;
    const int m0   = blockIdx.x * 128;
    const int n0   = blockIdx.y * 64;

    const uint4* gAh = (const uint4*)Ah;
    const uint4* gAl = (const uint4*)Al;
    const uint4* gBh = (const uint4*)Bh;
    const uint4* gBl = (const uint4*)Bl;

    // per-thread load coordinates
    const int ar0 = t >> 2, aj = t & 3;          // A: rows ar0, ar0+64
    const int br  = t >> 2, bj = t & 3;          // B: 64 rows x 4 uint4

    auto load_chunk = [&](int c, char* st) {
#pragma unroll
        for (int i = 0; i < 2; i++) {
            int r = ar0 + 64 * i;
            size_t gofs = (size_t)(m0 + r) * 64 + c * 4 + aj;
            cp_async16(st + GST_AH + r * (LDS_K * 2) + aj * 16, gAh + gofs);
            cp_async16(st + GST_AL + r * (LDS_K * 2) + aj * 16, gAl + gofs);
        }
        size_t gofs = (size_t)(n0 + br) * 64 + c * 4 + bj;
        cp_async16(st + GST_BH + br * (LDS_K * 2) + bj * 16, gBh + gofs);
        cp_async16(st + GST_BL + br * (LDS_K * 2) + bj * 16, gBl + gofs);
    };

    float acc[2][4][4];
#pragma unroll
    for (int i = 0; i < 2; i++)
#pragma unroll
        for (int j = 0; j < 4; j++)
#pragma unroll
            for (int e = 0; e < 4; e++) acc[i][j][e] = 0.f;

    const int LW = LDS_K / 2;

    // prologue: chunk 0 -> stage 0
    load_chunk(0, sm);
    CP_COMMIT();

    for (int c = 0; c < 16; c++) {
        __syncthreads();                 // stage (c+1)&1 free of readers
        if (c < 15) load_chunk(c + 1, sm + ((c + 1) & 1) * GST_SIZE);
        CP_COMMIT();
        CP_WAIT1();                      // chunk c resident
        __syncthreads();

        char* st = sm + (c & 1) * GST_SIZE;
        const uint32_t* sAh32 = (const uint32_t*)(st + GST_AH);
        const uint32_t* sAl32 = (const uint32_t*)(st + GST_AL);
        const uint32_t* sBh32 = (const uint32_t*)(st + GST_BH);
        const uint32_t* sBl32 = (const uint32_t*)(st + GST_BL);

#pragma unroll
        for (int ks = 0; ks < 2; ks++) {
            const int kw = ks * 8;
            uint32_t ah[2][4], al[2][4], bh[4][2], bl[4][2];
#pragma unroll
            for (int i = 0; i < 2; i++) {
                int row = wm * 32 + i * 16 + g;
                ah[i][0] = sAh32[row * LW + kw + tig];
                ah[i][1] = sAh32[(row + 8) * LW + kw + tig];
                ah[i][2] = sAh32[row * LW + kw + 4 + tig];
                ah[i][3] = sAh32[(row + 8) * LW + kw + 4 + tig];
                al[i][0] = sAl32[row * LW + kw + tig];
                al[i][1] = sAl32[(row + 8) * LW + kw + tig];
                al[i][2] = sAl32[row * LW + kw + 4 + tig];
                al[i][3] = sAl32[(row + 8) * LW + kw + 4 + tig];
            }
#pragma unroll
            for (int j = 0; j < 4; j++) {
                int row = wn * 32 + j * 8 + g;
                bh[j][0] = sBh32[row * LW + kw + tig];
                bh[j][1] = sBh32[row * LW + kw + 4 + tig];
                bl[j][0] = sBl32[row * LW + kw + tig];
                bl[j][1] = sBl32[row * LW + kw + 4 + tig];
            }
#pragma unroll
            for (int i = 0; i < 2; i++)
#pragma unroll
                for (int j = 0; j < 4; j++) {
                    mma_bf16(acc[i][j], ah[i], bh[j]);
                    mma_bf16(acc[i][j], ah[i], bl[j]);
                    mma_bf16(acc[i][j], al[i], bh[j]);
                }
        }
    }

    // ---- epilogue ----
#pragma unroll
    for (int i = 0; i < 2; i++) {
#pragma unroll
        for (int j = 0; j < 4; j++) {
            int row0 = m0 + wm * 32 + i * 16 + g;
            int col  = n0 + wn * 32 + j * 8 + tig * 2;
            if (MODE == 0) {
                const int mat = n0 >> 9;
                const int cc  = col & 511;
                const int h   = cc >> 6;
                const int dk  = cc & 63;
                const int bI  = row0 >> 10;
                const int nn0 = row0 & 1023;
                const int nn1 = (row0 + 8) & 1023;
                if (mat == 2) {
                    size_t vb = (size_t)((bI * NH + h) * DK + dk) * Nn;
                    __nv_bfloat16 hh, ll;
                    split1(acc[i][j][0], hh, ll); H2[vb + nn0] = hh; L2[vb + nn0] = ll;
                    split1(acc[i][j][2], hh, ll); H2[vb + nn1] = hh; L2[vb + nn1] = ll;
                    split1(acc[i][j][1], hh, ll); H2[vb + Nn + nn0] = hh; L2[vb + Nn + nn0] = ll;
                    split1(acc[i][j][3], hh, ll); H2[vb + Nn + nn1] = hh; L2[vb + Nn + nn1] = ll;
                } else {
                    __nv_bfloat16* BH = (mat == 0 ? H0 : H1);
                    __nv_bfloat16* BL = (mat == 0 ? L0 : L1);
                    size_t o0 = ((size_t)((bI * NH + h) * Nn + nn0)) * DK + dk;
                    size_t o1 = ((size_t)((bI * NH + h) * Nn + nn1)) * DK + dk;
                    uint32_t h0, l0, h1, l1;
                    split2(acc[i][j][0], acc[i][j][1], h0, l0);
                    split2(acc[i][j][2], acc[i][j][3], h1, l1);
                    *(uint32_t*)(BH + o0) = h0; *(uint32_t*)(BL + o0) = l0;
                    *(uint32_t*)(BH + o1) = h1; *(uint32_t*)(BL + o1) = l1;
                }
            } else {
                float* dst0 = Cf + (size_t)row0 * Dd + col;
                float* dst1 = Cf + (size_t)(row0 + 8) * Dd + col;
                *(float2*)dst0 = make_float2(acc[i][j][0], acc[i][j][1]);
                *(float2*)dst1 = make_float2(acc[i][j][2], acc[i][j][3]);
            }
        }
    }
}

// ---------------------------------------------------------------------------
// HMMA masked flash attention, cp.async double-buffered K/V.
// Grid (8, 64), 256 thr = 8 warps; warp owns 16 q rows. Key tile 64 x 16.
// Q fragments loaded directly from global (no Q smem).
// ---------------------------------------------------------------------------
#define ATT_PAD   72
#define AST_KH    0                      // per-stage offsets (bytes)
#define AST_KL    9216
#define AST_VTH   18432
#define AST_VTL   27648
#define AST_SIZE  36864
#define ATT_SMEM  (2 * AST_SIZE)         // 73728

__global__ __launch_bounds__(256, 1)
void attn_hmma(const __nv_bfloat16* __restrict__ Qh, const __nv_bfloat16* __restrict__ Ql,
               const __nv_bfloat16* __restrict__ Kh, const __nv_bfloat16* __restrict__ Kl,
               const __nv_bfloat16* __restrict__ VTh, const __nv_bfloat16* __restrict__ VTl,
               const uint32_t* __restrict__ mask,
               __nv_bfloat16* __restrict__ Oh, __nv_bfloat16* __restrict__ Ol) {
    extern __shared__ char sm[];

    const int t    = threadIdx.x;
    const int lane = t & 31;
    const int w    = t >> 5;
    const int g    = lane >> 2;
    const int tig  = lane & 3;
    const int bh   = blockIdx.y;
    const int bI   = bh >> 3;
    const int h    = bh & 7;
    const int q0   = blockIdx.x * 128;
    const int rw   = w * 16;

    const uint4* gKh  = (const uint4*)(Kh + (size_t)bh * Nn * DK);
    const uint4* gKl  = (const uint4*)(Kl + (size_t)bh * Nn * DK);
    const uint4* gVTh = (const uint4*)(VTh + (size_t)bh * DK * Nn);
    const uint4* gVTl = (const uint4*)(VTl + (size_t)bh * DK * Nn);
    const uint32_t* mrow0 = mask + ((size_t)(bI * Nn + q0 + rw + g)) * 32;
    const uint32_t* mrow1 = mrow0 + 8 * 32;

    // per-thread K/V load coordinates (512 slots, 2 per thread)
    const int lrow = t >> 3;             // 0..31 (+32 on second)
    const int lc8  = t & 7;

    auto load_tile = [&](int kt, char* st) {
#pragma unroll
        for (int i = 0; i < 2; i++) {
            int row = lrow + 32 * i;
            size_t gk = (size_t)(kt * 64 + row) * 8 + lc8;
            cp_async16(st + AST_KH + row * (ATT_PAD * 2) + lc8 * 16, gKh + gk);
            cp_async16(st + AST_KL + row * (ATT_PAD * 2) + lc8 * 16, gKl + gk);
            size_t gv = (size_t)row * 128 + kt * 8 + lc8;   // VT row = dk
            cp_async16(st + AST_VTH + row * (ATT_PAD * 2) + lc8 * 16, gVTh + gv);
            cp_async16(st + AST_VTL + row * (ATT_PAD * 2) + lc8 * 16, gVTl + gv);
        }
    };

    // ---- Q fragments straight from global ----
    uint32_t qh[4][4], ql[4][4];
    {
        const __nv_bfloat16* qbh = Qh + ((size_t)bh * Nn + q0 + rw + g) * DK;
        const __nv_bfloat16* qbl = Ql + ((size_t)bh * Nn + q0 + rw + g) * DK;
#pragma unroll
        for (int ks = 0; ks < 4; ks++) {
            int co = ks * 16 + 2 * tig;
            qh[ks][0] = *(const uint32_t*)(qbh + co);
            qh[ks][1] = *(const uint32_t*)(qbh + 8 * DK + co);
            qh[ks][2] = *(const uint32_t*)(qbh + co + 8);
            qh[ks][3] = *(const uint32_t*)(qbh + 8 * DK + co + 8);
            ql[ks][0] = *(const uint32_t*)(qbl + co);
            ql[ks][1] = *(const uint32_t*)(qbl + 8 * DK + co);
            ql[ks][2] = *(const uint32_t*)(qbl + co + 8);
            ql[ks][3] = *(const uint32_t*)(qbl + 8 * DK + co + 8);
        }
    }

    float m0 = -1e30f, m1 = -1e30f, l0 = 0.f, l1 = 0.f;
    float o[8][4];
#pragma unroll
    for (int j = 0; j < 8; j++)
#pragma unroll
        for (int e = 0; e < 4; e++) o[j][e] = 0.f;

    // prologue: tile 0 -> stage 0
    load_tile(0, sm);
    CP_COMMIT();

    for (int kt = 0; kt < 16; kt++) {
        __syncthreads();                 // stage (kt+1)&1 free of readers
        if (kt < 15) load_tile(kt + 1, sm + ((kt + 1) & 1) * AST_SIZE);
        CP_COMMIT();
        CP_WAIT1();                      // tile kt resident
        __syncthreads();

        char* st = sm + (kt & 1) * AST_SIZE;
        const __nv_bfloat16* sKh  = (const __nv_bfloat16*)(st + AST_KH);
        const __nv_bfloat16* sKl  = (const __nv_bfloat16*)(st + AST_KL);
        const __nv_bfloat16* sVth = (const __nv_bfloat16*)(st + AST_VTH);
        const __nv_bfloat16* sVtl = (const __nv_bfloat16*)(st + AST_VTL);

        // ---- S = Q K^T (3-term hi/lo) ----
        float sacc[8][4];
#pragma unroll
        for (int j = 0; j < 8; j++)
#pragma unroll
            for (int e = 0; e < 4; e++) sacc[j][e] = 0.f;
#pragma unroll
        for (int ks = 0; ks < 4; ks++) {
            int co = ks * 16 + 2 * tig;
#pragma unroll
            for (int j = 0; j < 8; j++) {
                int rb = (j * 8 + g) * ATT_PAD;
                uint32_t kb[2], klb[2];
                kb[0]  = *(const uint32_t*)(sKh + rb + co);
                kb[1]  = *(const uint32_t*)(sKh + rb + co + 8);
                klb[0] = *(const uint32_t*)(sKl + rb + co);
                klb[1] = *(const uint32_t*)(sKl + rb + co + 8);
                mma_bf16(sacc[j], qh[ks], kb);
                mma_bf16(sacc[j], qh[ks], klb);
                mma_bf16(sacc[j], ql[ks], kb);
            }
        }

        // ---- mask + online softmax ----
        uint32_t M00 = mrow0[2 * kt], M01 = mrow0[2 * kt + 1];
        uint32_t M10 = mrow1[2 * kt], M11 = mrow1[2 * kt + 1];
        float rmax0 = -1e30f, rmax1 = -1e30f;
#pragma unroll
        for (int j = 0; j < 8; j++) {
            int kb0 = j * 8 + 2 * tig;
            uint32_t w0 = (kb0 & 32) ? M01 : M00;
            uint32_t w1 = (kb0 & 32) ? M11 : M10;
            int sh = kb0 & 31;
            sacc[j][0] = ((w0 >> sh) & 1)       ? sacc[j][0] * 0.125f : -1e30f;
            sacc[j][1] = ((w0 >> (sh + 1)) & 1) ? sacc[j][1] * 0.125f : -1e30f;
            sacc[j][2] = ((w1 >> sh) & 1)       ? sacc[j][2] * 0.125f : -1e30f;
            sacc[j][3] = ((w1 >> (sh + 1)) & 1) ? sacc[j][3] * 0.125f : -1e30f;
            rmax0 = fmaxf(rmax0, fmaxf(sacc[j][0], sacc[j][1]));
            rmax1 = fmaxf(rmax1, fmaxf(sacc[j][2], sacc[j][3]));
        }
        rmax0 = fmaxf(rmax0, __shfl_xor_sync(0xFFFFFFFFu, rmax0, 1));
        rmax0 = fmaxf(rmax0, __shfl_xor_sync(0xFFFFFFFFu, rmax0, 2));
        rmax1 = fmaxf(rmax1, __shfl_xor_sync(0xFFFFFFFFu, rmax1, 1));
        rmax1 = fmaxf(rmax1, __shfl_xor_sync(0xFFFFFFFFu, rmax1, 2));
        float mn0 = fmaxf(m0, rmax0), mn1 = fmaxf(m1, rmax1);
        float al0 = __expf(m0 - mn0), al1 = __expf(m1 - mn1);
        m0 = mn0; m1 = mn1;
        float rs0 = 0.f, rs1 = 0.f;
#pragma unroll
        for (int j = 0; j < 8; j++) {
            float p0 = __expf(sacc[j][0] - mn0);
            float p1 = __expf(sacc[j][1] - mn0);
            float p2 = __expf(sacc[j][2] - mn1);
            float p3 = __expf(sacc[j][3] - mn1);
            sacc[j][0] = p0; sacc[j][1] = p1; sacc[j][2] = p2; sacc[j][3] = p3;
            rs0 += p0 + p1; rs1 += p2 + p3;
        }
        rs0 += __shfl_xor_sync(0xFFFFFFFFu, rs0, 1);
        rs0 += __shfl_xor_sync(0xFFFFFFFFu, rs0, 2);
        rs1 += __shfl_xor_sync(0xFFFFFFFFu, rs1, 1);
        rs1 += __shfl_xor_sync(0xFFFFFFFFu, rs1, 2);
        l0 = l0 * al0 + rs0; l1 = l1 * al1 + rs1;
#pragma unroll
        for (int j = 0; j < 8; j++) {
            o[j][0] *= al0; o[j][1] *= al0; o[j][2] *= al1; o[j][3] *= al1;
        }

        // ---- P (hi/lo thread-local repack) @ V (3-term) ----
#pragma unroll
        for (int ks = 0; ks < 4; ks++) {
            uint32_t ph[4], pl[4];
            float* f0 = sacc[2 * ks];
            float* f1 = sacc[2 * ks + 1];
            split2(f0[0], f0[1], ph[0], pl[0]);
            split2(f0[2], f0[3], ph[1], pl[1]);
            split2(f1[0], f1[1], ph[2], pl[2]);
            split2(f1[2], f1[3], ph[3], pl[3]);
            int kb = ks * 16 + 2 * tig;
#pragma unroll
            for (int j = 0; j < 8; j++) {
                int rb = (j * 8 + g) * ATT_PAD;
                uint32_t vb[2], vlb[2];
                vb[0]  = *(const uint32_t*)(sVth + rb + kb);
                vb[1]  = *(const uint32_t*)(sVth + rb + kb + 8);
                vlb[0] = *(const uint32_t*)(sVtl + rb + kb);
                vlb[1] = *(const uint32_t*)(sVtl + rb + kb + 8);
                mma_bf16(o[j], ph, vb);
                mma_bf16(o[j], pl, vb);
                mma_bf16(o[j], ph, vlb);
            }
        }
    }

    // ---- epilogue: normalize, relu, hi/lo split, write [b][q][h*64+dk] ----
    float inv0 = 1.f / l0, inv1 = 1.f / l1;
    size_t row0 = (size_t)(bI * Nn + q0 + rw + g);
    size_t row1 = row0 + 8;
#pragma unroll
    for (int j = 0; j < 8; j++) {
        int col = h * 64 + j * 8 + 2 * tig;
        float v00 = fmaxf(o[j][0] * inv0, 0.f);
        float v01 = fmaxf(o[j][1] * inv0, 0.f);
        float v10 = fmaxf(o[j][2] * inv1, 0.f);
        float v11 = fmaxf(o[j][3] * inv1, 0.f);
        uint32_t h0, lo0, h1, lo1;
        split2(v00, v01, h0, lo0);
        split2(v10, v11, h1, lo1);
        *(uint32_t*)(Oh + row0 * Dd + col) = h0;
        *(uint32_t*)(Ol + row0 * Dd + col) = lo0;
        *(uint32_t*)(Oh + row1 * Dd + col) = h1;
        *(uint32_t*)(Ol + row1 * Dd + col) = lo1;
    }
}

// ---------------------------------------------------------------------------
extern "C" void kernel_launch(void* const* d_in, const int* in_sizes, int n_in,
                              void* d_out, int out_size) {
    const float* x   = (const float*)d_in[0];
    const int*   adj = (const int*)d_in[1];
    const float* Wq  = (const float*)d_in[2];
    const float* Wk  = (const float*)d_in[3];
    const float* Wv  = (const float*)d_in[4];
    const float* Wo  = (const float*)d_in[5];
    float* out = (float*)d_out;

    __nv_bfloat16 *pxh, *pxl, *pWth, *pWtl, *pWoth, *pWotl;
    __nv_bfloat16 *pQh, *pQl, *pKh, *pKl, *pVTh, *pVTl, *patth, *pattl;
    uint32_t* pmask;
    cudaGetSymbolAddress((void**)&pxh, g_xh);
    cudaGetSymbolAddress((void**)&pxl, g_xl);
    cudaGetSymbolAddress((void**)&pWth, g_Wth);
    cudaGetSymbolAddress((void**)&pWtl, g_Wtl);
    cudaGetSymbolAddress((void**)&pWoth, g_Woth);
    cudaGetSymbolAddress((void**)&pWotl, g_Wotl);
    cudaGetSymbolAddress((void**)&pQh, g_Qh);
    cudaGetSymbolAddress((void**)&pQl, g_Ql);
    cudaGetSymbolAddress((void**)&pKh, g_Kh);
    cudaGetSymbolAddress((void**)&pKl, g_Kl);
    cudaGetSymbolAddress((void**)&pVTh, g_VTh);
    cudaGetSymbolAddress((void**)&pVTl, g_VTl);
    cudaGetSymbolAddress((void**)&patth, g_atth);
    cudaGetSymbolAddress((void**)&pattl, g_attl);
    cudaGetSymbolAddress((void**)&pmask, g_mask);

    cudaFuncSetAttribute(gemm_hmma<0>, cudaFuncAttributeMaxDynamicSharedMemorySize, GEMM_SMEM);
    cudaFuncSetAttribute(gemm_hmma<1>, cudaFuncAttributeMaxDynamicSharedMemorySize, GEMM_SMEM);
    cudaFuncSetAttribute(attn_hmma, cudaFuncAttributeMaxDynamicSharedMemorySize, ATT_SMEM);

    const int n4 = MROWS * Dd / 4;

    split_kernel<<<n4 / 256, 256>>>(x, pxh, pxl, n4);
    wsplit_kernel<<<1024, 256>>>(Wq, pWth, pWtl, 0);
    wsplit_kernel<<<1024, 256>>>(Wk, pWth, pWtl, 512);
    wsplit_kernel<<<1024, 256>>>(Wv, pWth, pWtl, 1024);
    wsplit_kernel<<<1024, 256>>>(Wo, pWoth, pWotl, 0);
    adjmask_kernel<<<(MROWS * 32) / 256, 256>>>(adj, pmask);

    gemm_hmma<0><<<dim3(MROWS / 128, 1536 / 64), 256, GEMM_SMEM>>>(
        pxh, pxl, pWth, pWtl, nullptr, pQh, pQl, pKh, pKl, pVTh, pVTl);

    attn_hmma<<<dim3(Nn / 128, Bb * NH), 256, ATT_SMEM>>>(
        pQh, pQl, pKh, pKl, pVTh, pVTl, pmask, patth, pattl);

    gemm_hmma<1><<<dim3(MROWS / 128, Dd / 64), 256, GEMM_SMEM>>>(
        patth, pattl, pWoth, pWotl, out,
        nullptr, nullptr, nullptr, nullptr, nullptr, nullptr);
}

// round 9
// speedup vs baseline: 2.6253x; 1.0235x over previous
#include <cuda_runtime.h>
#include <cuda_bf16.h>
#include <cstdint>
#include <cstddef>

// ---------------------------------------------------------------------------
// GATLayer: out = relu( MHA_masked(x; Wq,Wk,Wv, adj) ) @ Wo
// B=8, N=1024, D=512, NH=8, DK=64
// Round 8: occupancy 2 (launch_bounds cap 128 regs) on attn+gemm; merged
// weight-prep launches. cp.async double-buffered pipelines (round 7).
// All matmuls HMMA bf16 hi/lo x3; precomputed adj bitmasks; V pre-transposed.
// ---------------------------------------------------------------------------

#define Bb   8
#define Nn   1024
#define Dd   512
#define NH   8
#define DK   64
#define MROWS (Bb * Nn)          // 8192

// ---------------- scratch ----------------
__device__ __nv_bfloat16 g_xh[MROWS * Dd];
__device__ __nv_bfloat16 g_xl[MROWS * Dd];
__device__ __nv_bfloat16 g_Wth[3 * Dd * Dd];
__device__ __nv_bfloat16 g_Wtl[3 * Dd * Dd];
__device__ __nv_bfloat16 g_Woth[Dd * Dd];
__device__ __nv_bfloat16 g_Wotl[Dd * Dd];
__device__ __nv_bfloat16 g_Qh[Bb * NH * Nn * DK];
__device__ __nv_bfloat16 g_Ql[Bb * NH * Nn * DK];
__device__ __nv_bfloat16 g_Kh[Bb * NH * Nn * DK];
__device__ __nv_bfloat16 g_Kl[Bb * NH * Nn * DK];
__device__ __nv_bfloat16 g_VTh[Bb * NH * DK * Nn];   // [bh][dk][key]
__device__ __nv_bfloat16 g_VTl[Bb * NH * DK * Nn];
__device__ __nv_bfloat16 g_atth[MROWS * Dd];
__device__ __nv_bfloat16 g_attl[MROWS * Dd];
__device__ uint32_t g_mask[Bb * Nn * 32];            // packed adj bits

// ---------------------------------------------------------------------------
__device__ __forceinline__ void mma_bf16(float* c, const uint32_t* a, const uint32_t* b) {
    asm volatile(
        "mma.sync.aligned.m16n8k16.row.col.f32.bf16.bf16.f32 "
        "{%0,%1,%2,%3}, {%4,%5,%6,%7}, {%8,%9}, {%0,%1,%2,%3};"
        : "+f"(c[0]), "+f"(c[1]), "+f"(c[2]), "+f"(c[3])
        : "r"(a[0]), "r"(a[1]), "r"(a[2]), "r"(a[3]), "r"(b[0]), "r"(b[1]));
}

__device__ __forceinline__ void cp_async16(void* smem_dst, const void* gsrc) {
    uint32_t s = (uint32_t)__cvta_generic_to_shared(smem_dst);
    asm volatile("cp.async.cg.shared.global [%0], [%1], 16;" :: "r"(s), "l"(gsrc));
}
#define CP_COMMIT() asm volatile("cp.async.commit_group;" ::: "memory")
#define CP_WAIT1()  asm volatile("cp.async.wait_group 1;" ::: "memory")

__device__ __forceinline__ void split2(float a, float b, uint32_t& hi, uint32_t& lo) {
    __nv_bfloat16 ha = __float2bfloat16(a), hb = __float2bfloat16(b);
    __nv_bfloat16 la = __float2bfloat16(a - __bfloat162float(ha));
    __nv_bfloat16 lb = __float2bfloat16(b - __bfloat162float(hb));
    __nv_bfloat162 H(ha, hb), L(la, lb);
    hi = *(uint32_t*)&H; lo = *(uint32_t*)&L;
}
__device__ __forceinline__ void split1(float v, __nv_bfloat16& h, __nv_bfloat16& l) {
    h = __float2bfloat16(v);
    l = __float2bfloat16(v - __bfloat162float(h));
}

// ---------------------------------------------------------------------------
__global__ void split_kernel(const float* __restrict__ in,
                             __nv_bfloat16* __restrict__ hi,
                             __nv_bfloat16* __restrict__ lo, int n4) {
    int i = blockIdx.x * blockDim.x + threadIdx.x;
    if (i >= n4) return;
    float4 v = ((const float4*)in)[i];
    uint32_t h0, l0, h1, l1;
    split2(v.x, v.y, h0, l0);
    split2(v.z, v.w, h1, l1);
    uint32_t* H = (uint32_t*)hi;
    uint32_t* L = (uint32_t*)lo;
    H[2 * i] = h0; H[2 * i + 1] = h1;
    L[2 * i] = l0; L[2 * i + 1] = l1;
}

// all 4 weights transposed+split in ONE launch. blockIdx.y selects matrix.
__global__ void wsplit_all(const float* __restrict__ Wq, const float* __restrict__ Wk,
                           const float* __restrict__ Wv, const float* __restrict__ Wo,
                           __nv_bfloat16* __restrict__ th, __nv_bfloat16* __restrict__ tl,
                           __nv_bfloat16* __restrict__ oth, __nv_bfloat16* __restrict__ otl) {
    int t = blockIdx.x * blockDim.x + threadIdx.x;   // 512*512
    int m = blockIdx.y;                              // 0..3
    int k = t & 511, n = t >> 9;
    const float* W = (m == 0 ? Wq : (m == 1 ? Wk : (m == 2 ? Wv : Wo)));
    float v = W[(size_t)k * Dd + n];
    __nv_bfloat16 h, l;
    split1(v, h, l);
    if (m < 3) {
        th[(size_t)(m * 512 + n) * Dd + k] = h;
        tl[(size_t)(m * 512 + n) * Dd + k] = l;
    } else {
        oth[(size_t)n * Dd + k] = h;
        otl[(size_t)n * Dd + k] = l;
    }
}

// pack adj [8][1024][1024] int32 -> bitmask [8*1024][32] (warp per row)
__global__ void adjmask_kernel(const int* __restrict__ adj,
                               uint32_t* __restrict__ mask) {
    int row  = (blockIdx.x * blockDim.x + threadIdx.x) >> 5;
    int lane = threadIdx.x & 31;
    if (row >= Bb * Nn) return;
    const int* ar = adj + (size_t)row * Nn;
    uint32_t* mr = mask + (size_t)row * 32;
#pragma unroll
    for (int j = 0; j < 32; j++) {
        uint32_t b = __ballot_sync(0xFFFFFFFFu, ar[j * 32 + lane] != 0);
        if (lane == 0) mr[j] = b;
    }
}

// ---------------------------------------------------------------------------
// HMMA GEMM (CTA 128x64, BK=32, 8 warps 4m x 2n), cp.async double-buffered.
// MODE 0: QKV - Q/K head-major hi/lo; V TRANSPOSED [bh][dk][key].
// MODE 1: f32 row-major C.
// ---------------------------------------------------------------------------
#define LDS_K     40
#define GST_AH    0                      // per-stage offsets (bytes)
#define GST_AL    10240
#define GST_BH    20480
#define GST_BL    25600
#define GST_SIZE  30720
#define GEMM_SMEM (2 * GST_SIZE)         // 61440

template <int MODE>
__global__ __launch_bounds__(256, 2)
void gemm_hmma(const __nv_bfloat16* __restrict__ Ah, const __nv_bfloat16* __restrict__ Al,
               const __nv_bfloat16* __restrict__ Bh, const __nv_bfloat16* __restrict__ Bl,
               float* __restrict__ Cf,
               __nv_bfloat16* __restrict__ H0, __nv_bfloat16* __restrict__ L0,
               __nv_bfloat16* __restrict__ H1, __nv_bfloat16* __restrict__ L1,
               __nv_bfloat16* __restrict__ H2, __nv_bfloat16* __restrict__ L2) {
    extern __shared__ char sm[];

    const int t    = threadIdx.x;
    const int wid  = t >> 5;
    const int lane = t & 31;
    const int g    = lane >> 2;
    const int tig  = lane & 3;
    const int wm   = wid & 3;
    const int wn   = wid >> 2;
    const int m0   = blockIdx.x * 128;
    const int n0   = blockIdx.y * 64;

    const uint4* gAh = (const uint4*)Ah;
    const uint4* gAl = (const uint4*)Al;
    const uint4* gBh = (const uint4*)Bh;
    const uint4* gBl = (const uint4*)Bl;

    const int ar0 = t >> 2, aj = t & 3;
    const int br  = t >> 2, bj = t & 3;

    auto load_chunk = [&](int c, char* st) {
#pragma unroll
        for (int i = 0; i < 2; i++) {
            int r = ar0 + 64 * i;
            size_t gofs = (size_t)(m0 + r) * 64 + c * 4 + aj;
            cp_async16(st + GST_AH + r * (LDS_K * 2) + aj * 16, gAh + gofs);
            cp_async16(st + GST_AL + r * (LDS_K * 2) + aj * 16, gAl + gofs);
        }
        size_t gofs = (size_t)(n0 + br) * 64 + c * 4 + bj;
        cp_async16(st + GST_BH + br * (LDS_K * 2) + bj * 16, gBh + gofs);
        cp_async16(st + GST_BL + br * (LDS_K * 2) + bj * 16, gBl + gofs);
    };

    float acc[2][4][4];
#pragma unroll
    for (int i = 0; i < 2; i++)
#pragma unroll
        for (int j = 0; j < 4; j++)
#pragma unroll
            for (int e = 0; e < 4; e++) acc[i][j][e] = 0.f;

    const int LW = LDS_K / 2;

    load_chunk(0, sm);
    CP_COMMIT();

    for (int c = 0; c < 16; c++) {
        __syncthreads();
        if (c < 15) load_chunk(c + 1, sm + ((c + 1) & 1) * GST_SIZE);
        CP_COMMIT();
        CP_WAIT1();
        __syncthreads();

        char* st = sm + (c & 1) * GST_SIZE;
        const uint32_t* sAh32 = (const uint32_t*)(st + GST_AH);
        const uint32_t* sAl32 = (const uint32_t*)(st + GST_AL);
        const uint32_t* sBh32 = (const uint32_t*)(st + GST_BH);
        const uint32_t* sBl32 = (const uint32_t*)(st + GST_BL);

#pragma unroll
        for (int ks = 0; ks < 2; ks++) {
            const int kw = ks * 8;
            uint32_t ah[2][4], al[2][4], bh[4][2], bl[4][2];
#pragma unroll
            for (int i = 0; i < 2; i++) {
                int row = wm * 32 + i * 16 + g;
                ah[i][0] = sAh32[row * LW + kw + tig];
                ah[i][1] = sAh32[(row + 8) * LW + kw + tig];
                ah[i][2] = sAh32[row * LW + kw + 4 + tig];
                ah[i][3] = sAh32[(row + 8) * LW + kw + 4 + tig];
                al[i][0] = sAl32[row * LW + kw + tig];
                al[i][1] = sAl32[(row + 8) * LW + kw + tig];
                al[i][2] = sAl32[row * LW + kw + 4 + tig];
                al[i][3] = sAl32[(row + 8) * LW + kw + 4 + tig];
            }
#pragma unroll
            for (int j = 0; j < 4; j++) {
                int row = wn * 32 + j * 8 + g;
                bh[j][0] = sBh32[row * LW + kw + tig];
                bh[j][1] = sBh32[row * LW + kw + 4 + tig];
                bl[j][0] = sBl32[row * LW + kw + tig];
                bl[j][1] = sBl32[row * LW + kw + 4 + tig];
            }
#pragma unroll
            for (int i = 0; i < 2; i++)
#pragma unroll
                for (int j = 0; j < 4; j++) {
                    mma_bf16(acc[i][j], ah[i], bh[j]);
                    mma_bf16(acc[i][j], ah[i], bl[j]);
                    mma_bf16(acc[i][j], al[i], bh[j]);
                }
        }
    }

    // ---- epilogue ----
#pragma unroll
    for (int i = 0; i < 2; i++) {
#pragma unroll
        for (int j = 0; j < 4; j++) {
            int row0 = m0 + wm * 32 + i * 16 + g;
            int col  = n0 + wn * 32 + j * 8 + tig * 2;
            if (MODE == 0) {
                const int mat = n0 >> 9;
                const int cc  = col & 511;
                const int h   = cc >> 6;
                const int dk  = cc & 63;
                const int bI  = row0 >> 10;
                const int nn0 = row0 & 1023;
                const int nn1 = (row0 + 8) & 1023;
                if (mat == 2) {
                    size_t vb = (size_t)((bI * NH + h) * DK + dk) * Nn;
                    __nv_bfloat16 hh, ll;
                    split1(acc[i][j][0], hh, ll); H2[vb + nn0] = hh; L2[vb + nn0] = ll;
                    split1(acc[i][j][2], hh, ll); H2[vb + nn1] = hh; L2[vb + nn1] = ll;
                    split1(acc[i][j][1], hh, ll); H2[vb + Nn + nn0] = hh; L2[vb + Nn + nn0] = ll;
                    split1(acc[i][j][3], hh, ll); H2[vb + Nn + nn1] = hh; L2[vb + Nn + nn1] = ll;
                } else {
                    __nv_bfloat16* BH = (mat == 0 ? H0 : H1);
                    __nv_bfloat16* BL = (mat == 0 ? L0 : L1);
                    size_t o0 = ((size_t)((bI * NH + h) * Nn + nn0)) * DK + dk;
                    size_t o1 = ((size_t)((bI * NH + h) * Nn + nn1)) * DK + dk;
                    uint32_t h0, l0, h1, l1;
                    split2(acc[i][j][0], acc[i][j][1], h0, l0);
                    split2(acc[i][j][2], acc[i][j][3], h1, l1);
                    *(uint32_t*)(BH + o0) = h0; *(uint32_t*)(BL + o0) = l0;
                    *(uint32_t*)(BH + o1) = h1; *(uint32_t*)(BL + o1) = l1;
                }
            } else {
                float* dst0 = Cf + (size_t)row0 * Dd + col;
                float* dst1 = Cf + (size_t)(row0 + 8) * Dd + col;
                *(float2*)dst0 = make_float2(acc[i][j][0], acc[i][j][1]);
                *(float2*)dst1 = make_float2(acc[i][j][2], acc[i][j][3]);
            }
        }
    }
}

// ---------------------------------------------------------------------------
// HMMA masked flash attention, cp.async double-buffered K/V, occupancy 2.
// Grid (8, 64), 256 thr = 8 warps; warp owns 16 q rows. Key tile 64 x 16.
// Q fragments loaded directly from global (no Q smem).
// ---------------------------------------------------------------------------
#define ATT_PAD   72
#define AST_KH    0
#define AST_KL    9216
#define AST_VTH   18432
#define AST_VTL   27648
#define AST_SIZE  36864
#define ATT_SMEM  (2 * AST_SIZE)         // 73728

__global__ __launch_bounds__(256, 2)
void attn_hmma(const __nv_bfloat16* __restrict__ Qh, const __nv_bfloat16* __restrict__ Ql,
               const __nv_bfloat16* __restrict__ Kh, const __nv_bfloat16* __restrict__ Kl,
               const __nv_bfloat16* __restrict__ VTh, const __nv_bfloat16* __restrict__ VTl,
               const uint32_t* __restrict__ mask,
               __nv_bfloat16* __restrict__ Oh, __nv_bfloat16* __restrict__ Ol) {
    extern __shared__ char sm[];

    const int t    = threadIdx.x;
    const int lane = t & 31;
    const int w    = t >> 5;
    const int g    = lane >> 2;
    const int tig  = lane & 3;
    const int bh   = blockIdx.y;
    const int bI   = bh >> 3;
    const int h    = bh & 7;
    const int q0   = blockIdx.x * 128;
    const int rw   = w * 16;

    const uint4* gKh  = (const uint4*)(Kh + (size_t)bh * Nn * DK);
    const uint4* gKl  = (const uint4*)(Kl + (size_t)bh * Nn * DK);
    const uint4* gVTh = (const uint4*)(VTh + (size_t)bh * DK * Nn);
    const uint4* gVTl = (const uint4*)(VTl + (size_t)bh * DK * Nn);
    const uint32_t* mrow0 = mask + ((size_t)(bI * Nn + q0 + rw + g)) * 32;
    const uint32_t* mrow1 = mrow0 + 8 * 32;

    const int lrow = t >> 3;
    const int lc8  = t & 7;

    auto load_tile = [&](int kt, char* st) {
#pragma unroll
        for (int i = 0; i < 2; i++) {
            int row = lrow + 32 * i;
            size_t gk = (size_t)(kt * 64 + row) * 8 + lc8;
            cp_async16(st + AST_KH + row * (ATT_PAD * 2) + lc8 * 16, gKh + gk);
            cp_async16(st + AST_KL + row * (ATT_PAD * 2) + lc8 * 16, gKl + gk);
            size_t gv = (size_t)row * 128 + kt * 8 + lc8;
            cp_async16(st + AST_VTH + row * (ATT_PAD * 2) + lc8 * 16, gVTh + gv);
            cp_async16(st + AST_VTL + row * (ATT_PAD * 2) + lc8 * 16, gVTl + gv);
        }
    };

    uint32_t qh[4][4], ql[4][4];
    {
        const __nv_bfloat16* qbh = Qh + ((size_t)bh * Nn + q0 + rw + g) * DK;
        const __nv_bfloat16* qbl = Ql + ((size_t)bh * Nn + q0 + rw + g) * DK;
#pragma unroll
        for (int ks = 0; ks < 4; ks++) {
            int co = ks * 16 + 2 * tig;
            qh[ks][0] = *(const uint32_t*)(qbh + co);
            qh[ks][1] = *(const uint32_t*)(qbh + 8 * DK + co);
            qh[ks][2] = *(const uint32_t*)(qbh + co + 8);
            qh[ks][3] = *(const uint32_t*)(qbh + 8 * DK + co + 8);
            ql[ks][0] = *(const uint32_t*)(qbl + co);
            ql[ks][1] = *(const uint32_t*)(qbl + 8 * DK + co);
            ql[ks][2] = *(const uint32_t*)(qbl + co + 8);
            ql[ks][3] = *(const uint32_t*)(qbl + 8 * DK + co + 8);
        }
    }

    float m0 = -1e30f, m1 = -1e30f, l0 = 0.f, l1 = 0.f;
    float o[8][4];
#pragma unroll
    for (int j = 0; j < 8; j++)
#pragma unroll
        for (int e = 0; e < 4; e++) o[j][e] = 0.f;

    load_tile(0, sm);
    CP_COMMIT();

    for (int kt = 0; kt < 16; kt++) {
        __syncthreads();
        if (kt < 15) load_tile(kt + 1, sm + ((kt + 1) & 1) * AST_SIZE);
        CP_COMMIT();
        CP_WAIT1();
        __syncthreads();

        char* st = sm + (kt & 1) * AST_SIZE;
        const __nv_bfloat16* sKh  = (const __nv_bfloat16*)(st + AST_KH);
        const __nv_bfloat16* sKl  = (const __nv_bfloat16*)(st + AST_KL);
        const __nv_bfloat16* sVth = (const __nv_bfloat16*)(st + AST_VTH);
        const __nv_bfloat16* sVtl = (const __nv_bfloat16*)(st + AST_VTL);

        // ---- S = Q K^T (3-term hi/lo) ----
        float sacc[8][4];
#pragma unroll
        for (int j = 0; j < 8; j++)
#pragma unroll
            for (int e = 0; e < 4; e++) sacc[j][e] = 0.f;
#pragma unroll
        for (int ks = 0; ks < 4; ks++) {
            int co = ks * 16 + 2 * tig;
#pragma unroll
            for (int j = 0; j < 8; j++) {
                int rb = (j * 8 + g) * ATT_PAD;
                uint32_t kb[2], klb[2];
                kb[0]  = *(const uint32_t*)(sKh + rb + co);
                kb[1]  = *(const uint32_t*)(sKh + rb + co + 8);
                klb[0] = *(const uint32_t*)(sKl + rb + co);
                klb[1] = *(const uint32_t*)(sKl + rb + co + 8);
                mma_bf16(sacc[j], qh[ks], kb);
                mma_bf16(sacc[j], qh[ks], klb);
                mma_bf16(sacc[j], ql[ks], kb);
            }
        }

        // ---- mask + online softmax ----
        uint32_t M00 = mrow0[2 * kt], M01 = mrow0[2 * kt + 1];
        uint32_t M10 = mrow1[2 * kt], M11 = mrow1[2 * kt + 1];
        float rmax0 = -1e30f, rmax1 = -1e30f;
#pragma unroll
        for (int j = 0; j < 8; j++) {
            int kb0 = j * 8 + 2 * tig;
            uint32_t w0 = (kb0 & 32) ? M01 : M00;
            uint32_t w1 = (kb0 & 32) ? M11 : M10;
            int sh = kb0 & 31;
            sacc[j][0] = ((w0 >> sh) & 1)       ? sacc[j][0] * 0.125f : -1e30f;
            sacc[j][1] = ((w0 >> (sh + 1)) & 1) ? sacc[j][1] * 0.125f : -1e30f;
            sacc[j][2] = ((w1 >> sh) & 1)       ? sacc[j][2] * 0.125f : -1e30f;
            sacc[j][3] = ((w1 >> (sh + 1)) & 1) ? sacc[j][3] * 0.125f : -1e30f;
            rmax0 = fmaxf(rmax0, fmaxf(sacc[j][0], sacc[j][1]));
            rmax1 = fmaxf(rmax1, fmaxf(sacc[j][2], sacc[j][3]));
        }
        rmax0 = fmaxf(rmax0, __shfl_xor_sync(0xFFFFFFFFu, rmax0, 1));
        rmax0 = fmaxf(rmax0, __shfl_xor_sync(0xFFFFFFFFu, rmax0, 2));
        rmax1 = fmaxf(rmax1, __shfl_xor_sync(0xFFFFFFFFu, rmax1, 1));
        rmax1 = fmaxf(rmax1, __shfl_xor_sync(0xFFFFFFFFu, rmax1, 2));
        float mn0 = fmaxf(m0, rmax0), mn1 = fmaxf(m1, rmax1);
        float al0 = __expf(m0 - mn0), al1 = __expf(m1 - mn1);
        m0 = mn0; m1 = mn1;
        float rs0 = 0.f, rs1 = 0.f;
#pragma unroll
        for (int j = 0; j < 8; j++) {
            float p0 = __expf(sacc[j][0] - mn0);
            float p1 = __expf(sacc[j][1] - mn0);
            float p2 = __expf(sacc[j][2] - mn1);
            float p3 = __expf(sacc[j][3] - mn1);
            sacc[j][0] = p0; sacc[j][1] = p1; sacc[j][2] = p2; sacc[j][3] = p3;
            rs0 += p0 + p1; rs1 += p2 + p3;
        }
        rs0 += __shfl_xor_sync(0xFFFFFFFFu, rs0, 1);
        rs0 += __shfl_xor_sync(0xFFFFFFFFu, rs0, 2);
        rs1 += __shfl_xor_sync(0xFFFFFFFFu, rs1, 1);
        rs1 += __shfl_xor_sync(0xFFFFFFFFu, rs1, 2);
        l0 = l0 * al0 + rs0; l1 = l1 * al1 + rs1;
#pragma unroll
        for (int j = 0; j < 8; j++) {
            o[j][0] *= al0; o[j][1] *= al0; o[j][2] *= al1; o[j][3] *= al1;
        }

        // ---- P (hi/lo thread-local repack) @ V (3-term) ----
#pragma unroll
        for (int ks = 0; ks < 4; ks++) {
            uint32_t ph[4], pl[4];
            float* f0 = sacc[2 * ks];
            float* f1 = sacc[2 * ks + 1];
            split2(f0[0], f0[1], ph[0], pl[0]);
            split2(f0[2], f0[3], ph[1], pl[1]);
            split2(f1[0], f1[1], ph[2], pl[2]);
            split2(f1[2], f1[3], ph[3], pl[3]);
            int kb = ks * 16 + 2 * tig;
#pragma unroll
            for (int j = 0; j < 8; j++) {
                int rb = (j * 8 + g) * ATT_PAD;
                uint32_t vb[2], vlb[2];
                vb[0]  = *(const uint32_t*)(sVth + rb + kb);
                vb[1]  = *(const uint32_t*)(sVth + rb + kb + 8);
                vlb[0] = *(const uint32_t*)(sVtl + rb + kb);
                vlb[1] = *(const uint32_t*)(sVtl + rb + kb + 8);
                mma_bf16(o[j], ph, vb);
                mma_bf16(o[j], pl, vb);
                mma_bf16(o[j], ph, vlb);
            }
        }
    }

    // ---- epilogue: normalize, relu, hi/lo split, write [b][q][h*64+dk] ----
    float inv0 = 1.f / l0, inv1 = 1.f / l1;
    size_t row0 = (size_t)(bI * Nn + q0 + rw + g);
    size_t row1 = row0 + 8;
#pragma unroll
    for (int j = 0; j < 8; j++) {
        int col = h * 64 + j * 8 + 2 * tig;
        float v00 = fmaxf(o[j][0] * inv0, 0.f);
        float v01 = fmaxf(o[j][1] * inv0, 0.f);
        float v10 = fmaxf(o[j][2] * inv1, 0.f);
        float v11 = fmaxf(o[j][3] * inv1, 0.f);
        uint32_t h0, lo0, h1, lo1;
        split2(v00, v01, h0, lo0);
        split2(v10, v11, h1, lo1);
        *(uint32_t*)(Oh + row0 * Dd + col) = h0;
        *(uint32_t*)(Ol + row0 * Dd + col) = lo0;
        *(uint32_t*)(Oh + row1 * Dd + col) = h1;
        *(uint32_t*)(Ol + row1 * Dd + col) = lo1;
    }
}

// ---------------------------------------------------------------------------
extern "C" void kernel_launch(void* const* d_in, const int* in_sizes, int n_in,
                              void* d_out, int out_size) {
    const float* x   = (const float*)d_in[0];
    const int*   adj = (const int*)d_in[1];
    const float* Wq  = (const float*)d_in[2];
    const float* Wk  = (const float*)d_in[3];
    const float* Wv  = (const float*)d_in[4];
    const float* Wo  = (const float*)d_in[5];
    float* out = (float*)d_out;

    __nv_bfloat16 *pxh, *pxl, *pWth, *pWtl, *pWoth, *pWotl;
    __nv_bfloat16 *pQh, *pQl, *pKh, *pKl, *pVTh, *pVTl, *patth, *pattl;
    uint32_t* pmask;
    cudaGetSymbolAddress((void**)&pxh, g_xh);
    cudaGetSymbolAddress((void**)&pxl, g_xl);
    cudaGetSymbolAddress((void**)&pWth, g_Wth);
    cudaGetSymbolAddress((void**)&pWtl, g_Wtl);
    cudaGetSymbolAddress((void**)&pWoth, g_Woth);
    cudaGetSymbolAddress((void**)&pWotl, g_Wotl);
    cudaGetSymbolAddress((void**)&pQh, g_Qh);
    cudaGetSymbolAddress((void**)&pQl, g_Ql);
    cudaGetSymbolAddress((void**)&pKh, g_Kh);
    cudaGetSymbolAddress((void**)&pKl, g_Kl);
    cudaGetSymbolAddress((void**)&pVTh, g_VTh);
    cudaGetSymbolAddress((void**)&pVTl, g_VTl);
    cudaGetSymbolAddress((void**)&patth, g_atth);
    cudaGetSymbolAddress((void**)&pattl, g_attl);
    cudaGetSymbolAddress((void**)&pmask, g_mask);

    cudaFuncSetAttribute(gemm_hmma<0>, cudaFuncAttributeMaxDynamicSharedMemorySize, GEMM_SMEM);
    cudaFuncSetAttribute(gemm_hmma<1>, cudaFuncAttributeMaxDynamicSharedMemorySize, GEMM_SMEM);
    cudaFuncSetAttribute(attn_hmma, cudaFuncAttributeMaxDynamicSharedMemorySize, ATT_SMEM);

    const int n4 = MROWS * Dd / 4;

    split_kernel<<<n4 / 256, 256>>>(x, pxh, pxl, n4);
    wsplit_all<<<dim3(1024, 4), 256>>>(Wq, Wk, Wv, Wo, pWth, pWtl, pWoth, pWotl);
    adjmask_kernel<<<(MROWS * 32) / 256, 256>>>(adj, pmask);

    gemm_hmma<0><<<dim3(MROWS / 128, 1536 / 64), 256, GEMM_SMEM>>>(
        pxh, pxl, pWth, pWtl, nullptr, pQh, pQl, pKh, pKl, pVTh, pVTl);

    attn_hmma<<<dim3(Nn / 128, Bb * NH), 256, ATT_SMEM>>>(
        pQh, pQl, pKh, pKl, pVTh, pVTl, pmask, patth, pattl);

    gemm_hmma<1><<<dim3(MROWS / 128, Dd / 64), 256, GEMM_SMEM>>>(
        patth, pattl, pWoth, pWotl, out,
        nullptr, nullptr, nullptr, nullptr, nullptr, nullptr);
}